// round 1
// baseline (speedup 1.0000x reference)
#include <cuda_runtime.h>
#include <cuda_bf16.h>
#include <stdint.h>
#include <math.h>

typedef __nv_bfloat16 bf16;

#define Bc   8
#define Sc   1024
#define Hc   1024
#define NHc  16
#define DHc  64
#define MLPc 4096
#define MROWS (Bc*Sc)   // 8192

// ---------------- device scratch (static: no allocations allowed) ----------------
__device__ bf16  g_wq[Hc*3*Hc];
__device__ bf16  g_wo[Hc*Hc];
__device__ bf16  g_w1[Hc*MLPc];
__device__ bf16  g_w2[MLPc*Hc];
__device__ float g_cm[Bc*6*Hc];
__device__ bf16  g_xmod[MROWS*Hc];
__device__ bf16  g_q[Bc*NHc*Sc*DHc];
__device__ bf16  g_k[Bc*NHc*Sc*DHc];
__device__ bf16  g_v[Bc*NHc*Sc*DHc];
__device__ bf16  g_y[MROWS*Hc];
__device__ float g_xres[MROWS*Hc];
__device__ bf16  g_h[(size_t)MROWS*MLPc];
// acc[0]=sumsq_x, [1]=sum(1/l) maxw, [2]=sumsq_attn, [3]=sumsq_x_after_attn,
// [4]=sumsq_relu, [5]=sumsq_mlp
__device__ float g_acc[8];
__device__ int   g_pos[MLPc];

// ---------------- helpers ----------------
__device__ __forceinline__ float block_sum256(float v, float* sm8) {
    #pragma unroll
    for (int o = 16; o > 0; o >>= 1) v += __shfl_xor_sync(0xffffffffu, v, o);
    __syncthreads();                       // protect sm8 reuse across calls
    if ((threadIdx.x & 31) == 0) sm8[threadIdx.x >> 5] = v;
    __syncthreads();
    float r = 0.f;
    #pragma unroll
    for (int i = 0; i < 8; i++) r += sm8[i];
    return r;
}

__device__ __forceinline__ void mma16816(float c[4], const uint32_t a[4],
                                         uint32_t b0, uint32_t b1) {
    asm volatile(
        "mma.sync.aligned.m16n8k16.row.col.f32.bf16.bf16.f32 "
        "{%0,%1,%2,%3},{%4,%5,%6,%7},{%8,%9},{%0,%1,%2,%3};\n"
        : "+f"(c[0]), "+f"(c[1]), "+f"(c[2]), "+f"(c[3])
        : "r"(a[0]), "r"(a[1]), "r"(a[2]), "r"(a[3]), "r"(b0), "r"(b1));
}

__device__ __forceinline__ uint32_t pack_bf162(float x, float y) {
    __nv_bfloat162 h = __floats2bfloat162_rn(x, y);
    return *(uint32_t*)&h;
}

// ---------------- small kernels ----------------
__global__ void k_zero() {
    int i = blockIdx.x * 256 + threadIdx.x;
    if (i < MLPc) g_pos[i] = 0;
    if (i < 8)    g_acc[i] = 0.f;
}

__global__ void k_conv(const float* __restrict__ s, int sel, int n) {
    bf16* d = (sel == 0) ? g_wq : (sel == 1) ? g_wo : (sel == 2) ? g_w1 : g_w2;
    int i = blockIdx.x * blockDim.x + threadIdx.x;
    if (i < n) d[i] = __float2bfloat16(s[i]);
}

// cm[b][j] = sum_k silu(c[b][k]) * w_cond[k][j],  j in [0,6144)
__global__ void k_cond(const float* __restrict__ c, const float* __restrict__ w) {
    __shared__ float ssil[Bc * Hc];     // 32 KB
    int tid = threadIdx.x;
    for (int i = tid; i < Bc * Hc; i += 256) {
        float v = c[i];
        ssil[i] = v / (1.f + expf(-v));
    }
    __syncthreads();
    int j = blockIdx.x * 256 + tid;
    float acc[Bc];
    #pragma unroll
    for (int b = 0; b < Bc; b++) acc[b] = 0.f;
    for (int k = 0; k < Hc; k++) {
        float wv = w[(size_t)k * (6 * Hc) + j];
        #pragma unroll
        for (int b = 0; b < Bc; b++) acc[b] += ssil[b * Hc + k] * wv;
    }
    #pragma unroll
    for (int b = 0; b < Bc; b++) g_cm[b * 6 * Hc + j] = acc[b];
}

// LayerNorm (no scale/bias, fp32 stats, bf16 output) + adaLN modulate -> bf16
__device__ __forceinline__ void ln_impl(const float* __restrict__ xin,
                                        bf16* __restrict__ xout,
                                        int so, int sco, float* ssq) {
    __shared__ float sm8[8];
    int row = blockIdx.x;
    int b = row >> 10;
    int tid = threadIdx.x;
    const float* xr = xin + (size_t)row * Hc;
    float v[4];
    #pragma unroll
    for (int i = 0; i < 4; i++) v[i] = xr[tid + i * 256];
    float s = v[0] + v[1] + v[2] + v[3];
    float mean = block_sum256(s, sm8) * (1.f / 1024.f);
    float s2 = 0.f;
    #pragma unroll
    for (int i = 0; i < 4; i++) { float d = v[i] - mean; s2 += d * d; }
    float var = block_sum256(s2, sm8) * (1.f / 1024.f);
    float rstd = rsqrtf(var + 1e-6f);
    const float* cmb = g_cm + b * 6 * Hc;
    #pragma unroll
    for (int i = 0; i < 4; i++) {
        int col = tid + i * 256;
        float lnv = __bfloat162float(__float2bfloat16((v[i] - mean) * rstd));
        float xm = lnv * cmb[sco * Hc + col] + cmb[so * Hc + col];
        xout[(size_t)row * Hc + col] = __float2bfloat16(xm);
    }
    if (ssq) {
        float q = v[0]*v[0] + v[1]*v[1] + v[2]*v[2] + v[3]*v[3];
        float t = block_sum256(q, sm8);
        if (tid == 0) atomicAdd(ssq, t);
    }
}
__global__ void k_ln1(const float* __restrict__ x) { ln_impl(x, g_xmod, 0, 1, &g_acc[0]); }
__global__ void k_ln2()                             { ln_impl(g_xres, g_xmod, 3, 4, &g_acc[3]); }

// ---------------- GEMM core: C[128x128] tile, bf16 mma.sync, fp32 accum ----------
// 256 threads = 8 warps arranged 4(m) x 2(n); each warp 32x64; BK=32.
__device__ __forceinline__ void gemm_core(const bf16* __restrict__ A,
                                          const bf16* __restrict__ Bm,
                                          int K, int N, int tileM, int tileN,
                                          bf16 (*As)[40], bf16 (*Bt)[40],
                                          float acc[2][8][4]) {
    const int tid = threadIdx.x, lane = tid & 31, warp = tid >> 5;
    const int wm = warp & 3, wn = warp >> 2;
    const int qd = lane >> 2, c2 = (lane & 3) << 1;
    #pragma unroll
    for (int mf = 0; mf < 2; mf++)
        #pragma unroll
        for (int nf = 0; nf < 8; nf++)
            #pragma unroll
            for (int i = 0; i < 4; i++) acc[mf][nf][i] = 0.f;

    for (int kt = 0; kt < K; kt += 32) {
        __syncthreads();
        // A tile: 128 x 32, 16B chunks
        #pragma unroll
        for (int t = 0; t < 2; t++) {
            int ch = tid + t * 256;               // 512 chunks
            int row = ch >> 2, kc = ch & 3;
            uint4 u = *(const uint4*)(A + (size_t)(tileM + row) * K + kt + kc * 8);
            *(uint4*)(&As[row][kc * 8]) = u;
        }
        // B tile: 32 x 128, stored n-major (transposed) for k-contiguous frags
        #pragma unroll
        for (int t = 0; t < 2; t++) {
            int ch = tid + t * 256;
            int row = ch >> 4, nc = ch & 15;      // row = k (0..31), nc*8 = n
            uint4 u = *(const uint4*)(Bm + (size_t)(kt + row) * N + tileN + nc * 8);
            const bf16* pv = (const bf16*)&u;
            #pragma unroll
            for (int i = 0; i < 8; i++) Bt[nc * 8 + i][row] = pv[i];
        }
        __syncthreads();
        #pragma unroll
        for (int kk = 0; kk < 2; kk++) {
            int kb = kk * 16;
            uint32_t af[2][4];
            #pragma unroll
            for (int mf = 0; mf < 2; mf++) {
                int ra = wm * 32 + mf * 16 + qd;
                af[mf][0] = *(const uint32_t*)(&As[ra][kb + c2]);
                af[mf][1] = *(const uint32_t*)(&As[ra + 8][kb + c2]);
                af[mf][2] = *(const uint32_t*)(&As[ra][kb + c2 + 8]);
                af[mf][3] = *(const uint32_t*)(&As[ra + 8][kb + c2 + 8]);
            }
            #pragma unroll
            for (int nf = 0; nf < 8; nf++) {
                int nb = wn * 64 + nf * 8 + qd;
                uint32_t b0 = *(const uint32_t*)(&Bt[nb][kb + c2]);
                uint32_t b1 = *(const uint32_t*)(&Bt[nb][kb + c2 + 8]);
                mma16816(acc[0][nf], af[0], b0, b1);
                mma16816(acc[1][nf], af[1], b0, b1);
            }
        }
    }
    __syncthreads();
}

#define GEMM_EPI_COORDS                                             \
    const int lane = threadIdx.x & 31, warp = threadIdx.x >> 5;     \
    const int wm = warp & 3, wn = warp >> 2;                        \
    const int qd = lane >> 2, c2 = (lane & 3) << 1;                 \
    const int tileM = blockIdx.y * 128, tileN = blockIdx.x * 128;

// qkv: split cols (k,q,v), scale q by 1/8, scatter to [b,h,s,d]
__global__ void k_qkv() {
    __shared__ bf16 As[128][40], Bt[128][40];
    float acc[2][8][4];
    gemm_core(g_xmod, g_wq, Hc, 3 * Hc, blockIdx.y * 128, blockIdx.x * 128, As, Bt, acc);
    GEMM_EPI_COORDS
    #pragma unroll
    for (int mf = 0; mf < 2; mf++)
        #pragma unroll
        for (int nf = 0; nf < 8; nf++)
            #pragma unroll
            for (int i = 0; i < 4; i++) {
                int r  = tileM + wm * 32 + mf * 16 + qd + ((i >> 1) << 3);
                int cc = tileN + wn * 64 + nf * 8 + c2 + (i & 1);
                int t = cc >> 10, rem = cc & 1023;
                int hh = rem >> 6, d = rem & 63;
                int b = r >> 10, s = r & 1023;
                float val = acc[mf][nf][i];
                size_t o = (((size_t)(b * NHc + hh)) * Sc + s) * DHc + d;
                if (t == 0)      g_k[o] = __float2bfloat16(val);
                else if (t == 1) g_q[o] = __float2bfloat16(val * 0.125f);
                else             g_v[o] = __float2bfloat16(val);
            }
}

// y @ w_attn_out: x_res = x + gate_msa*acc ; sumsq_attn
__global__ void k_attnout(const float* __restrict__ x_in) {
    __shared__ bf16 As[128][40], Bt[128][40];
    __shared__ float sm8[8];
    float acc[2][8][4];
    gemm_core(g_y, g_wo, Hc, Hc, blockIdx.y * 128, blockIdx.x * 128, As, Bt, acc);
    GEMM_EPI_COORDS
    float ss = 0.f;
    #pragma unroll
    for (int mf = 0; mf < 2; mf++)
        #pragma unroll
        for (int nf = 0; nf < 8; nf++)
            #pragma unroll
            for (int i = 0; i < 4; i++) {
                int r  = tileM + wm * 32 + mf * 16 + qd + ((i >> 1) << 3);
                int cc = tileN + wn * 64 + nf * 8 + c2 + (i & 1);
                int b = r >> 10;
                float g = g_cm[b * 6 * Hc + 2 * Hc + cc];
                float a = g * acc[mf][nf][i];
                size_t idx = (size_t)r * Hc + cc;
                g_xres[idx] = x_in[idx] + a;
                ss += a * a;
            }
    float t = block_sum256(ss, sm8);
    if (threadIdx.x == 0) atomicAdd(&g_acc[2], t);
}

// mlp1: positive counts per channel, sumsq_relu, tanh-gelu -> bf16 h
__global__ void k_mlp1() {
    __shared__ bf16 As[128][40], Bt[128][40];
    __shared__ float sm8[8];
    __shared__ int scnt[128];
    float acc[2][8][4];
    gemm_core(g_xmod, g_w1, Hc, MLPc, blockIdx.y * 128, blockIdx.x * 128, As, Bt, acc);
    GEMM_EPI_COORDS
    if (threadIdx.x < 128) scnt[threadIdx.x] = 0;
    __syncthreads();
    float ss = 0.f;
    #pragma unroll
    for (int nf = 0; nf < 8; nf++) {
        int cnt0 = 0, cnt1 = 0;
        #pragma unroll
        for (int mf = 0; mf < 2; mf++)
            #pragma unroll
            for (int i = 0; i < 4; i++) {
                float t = acc[mf][nf][i];
                ss += t * t;
                if (i & 1) cnt1 += (t > 0.f); else cnt0 += (t > 0.f);
                float u = 0.7978845608028654f * (t + 0.044715f * t * t * t);
                float gl = 0.5f * t * (1.f + tanhf(u));
                int r  = tileM + wm * 32 + mf * 16 + qd + ((i >> 1) << 3);
                int cc = tileN + wn * 64 + nf * 8 + c2 + (i & 1);
                g_h[(size_t)r * MLPc + cc] = __float2bfloat16(gl);
            }
        atomicAdd(&scnt[wn * 64 + nf * 8 + c2], cnt0);
        atomicAdd(&scnt[wn * 64 + nf * 8 + c2 + 1], cnt1);
    }
    __syncthreads();
    if (threadIdx.x < 128) atomicAdd(&g_pos[tileN + threadIdx.x], scnt[threadIdx.x]);
    float t = block_sum256(ss, sm8);
    if (threadIdx.x == 0) atomicAdd(&g_acc[4], t);
}

// mlp2: out = x_res + gate_mlp*acc ; sumsq_mlp
__global__ void k_mlp2(float* __restrict__ out) {
    __shared__ bf16 As[128][40], Bt[128][40];
    __shared__ float sm8[8];
    float acc[2][8][4];
    gemm_core(g_h, g_w2, MLPc, Hc, blockIdx.y * 128, blockIdx.x * 128, As, Bt, acc);
    GEMM_EPI_COORDS
    float ss = 0.f;
    #pragma unroll
    for (int mf = 0; mf < 2; mf++)
        #pragma unroll
        for (int nf = 0; nf < 8; nf++)
            #pragma unroll
            for (int i = 0; i < 4; i++) {
                int r  = tileM + wm * 32 + mf * 16 + qd + ((i >> 1) << 3);
                int cc = tileN + wn * 64 + nf * 8 + c2 + (i & 1);
                int b = r >> 10;
                float g = g_cm[b * 6 * Hc + 5 * Hc + cc];
                float m = g * acc[mf][nf][i];
                size_t idx = (size_t)r * Hc + cc;
                out[idx] = g_xres[idx] + m;
                ss += m * m;
            }
    float t = block_sum256(ss, sm8);
    if (threadIdx.x == 0) atomicAdd(&g_acc[5], t);
}

// ---------------- flash attention: one CTA per (b,h, 128 q rows) -----------------
__global__ void k_attn() {
    __shared__ bf16 Qs[128][72], Ks[64][72], Vt[64][72];
    __shared__ float sm8[8];
    const int tid = threadIdx.x, lane = tid & 31, w = tid >> 5;
    const int qd = lane >> 2, c2 = (lane & 3) << 1;
    const int bh = blockIdx.y, qt = blockIdx.x;

    const bf16* Qg = g_q + ((size_t)bh * Sc + qt * 128) * DHc;
    #pragma unroll
    for (int t = 0; t < 4; t++) {
        int ch = tid + t * 256;
        int row = ch >> 3, dc = ch & 7;
        *(uint4*)&Qs[row][dc * 8] = *(const uint4*)(Qg + row * DHc + dc * 8);
    }
    __syncthreads();

    uint32_t qa[4][4];
    {
        int ra = w * 16 + qd;
        #pragma unroll
        for (int kk = 0; kk < 4; kk++) {
            int kb = kk * 16;
            qa[kk][0] = *(const uint32_t*)&Qs[ra][kb + c2];
            qa[kk][1] = *(const uint32_t*)&Qs[ra + 8][kb + c2];
            qa[kk][2] = *(const uint32_t*)&Qs[ra][kb + c2 + 8];
            qa[kk][3] = *(const uint32_t*)&Qs[ra + 8][kb + c2 + 8];
        }
    }
    float O[8][4];
    #pragma unroll
    for (int nf = 0; nf < 8; nf++)
        #pragma unroll
        for (int i = 0; i < 4; i++) O[nf][i] = 0.f;
    float m0 = -1e30f, m1 = -1e30f, l0 = 0.f, l1 = 0.f;

    for (int kt = 0; kt < Sc / 64; kt++) {
        __syncthreads();
        const bf16* Kg = g_k + ((size_t)bh * Sc + kt * 64) * DHc;
        const bf16* Vg = g_v + ((size_t)bh * Sc + kt * 64) * DHc;
        #pragma unroll
        for (int t = 0; t < 2; t++) {
            int ch = tid + t * 256;
            int row = ch >> 3, dc = ch & 7;
            *(uint4*)&Ks[row][dc * 8] = *(const uint4*)(Kg + row * DHc + dc * 8);
            uint4 u = *(const uint4*)(Vg + row * DHc + dc * 8);
            const bf16* pv = (const bf16*)&u;
            #pragma unroll
            for (int i = 0; i < 8; i++) Vt[dc * 8 + i][row] = pv[i];
        }
        __syncthreads();

        float L[8][4];
        #pragma unroll
        for (int nf = 0; nf < 8; nf++) {
            L[nf][0] = L[nf][1] = L[nf][2] = L[nf][3] = 0.f;
            int nb = nf * 8 + qd;
            #pragma unroll
            for (int kk = 0; kk < 4; kk++) {
                uint32_t b0 = *(const uint32_t*)&Ks[nb][kk * 16 + c2];
                uint32_t b1 = *(const uint32_t*)&Ks[nb][kk * 16 + c2 + 8];
                mma16816(L[nf], qa[kk], b0, b1);
            }
        }
        // online softmax (rows qd and qd+8 within warp tile, shared across quad)
        float tm0 = -1e30f, tm1 = -1e30f;
        #pragma unroll
        for (int nf = 0; nf < 8; nf++) {
            tm0 = fmaxf(tm0, fmaxf(L[nf][0], L[nf][1]));
            tm1 = fmaxf(tm1, fmaxf(L[nf][2], L[nf][3]));
        }
        tm0 = fmaxf(tm0, __shfl_xor_sync(0xffffffffu, tm0, 1));
        tm0 = fmaxf(tm0, __shfl_xor_sync(0xffffffffu, tm0, 2));
        tm1 = fmaxf(tm1, __shfl_xor_sync(0xffffffffu, tm1, 1));
        tm1 = fmaxf(tm1, __shfl_xor_sync(0xffffffffu, tm1, 2));
        float mn0 = fmaxf(m0, tm0), mn1 = fmaxf(m1, tm1);
        float cor0 = expf(m0 - mn0), cor1 = expf(m1 - mn1);
        float s0 = 0.f, s1 = 0.f;
        #pragma unroll
        for (int nf = 0; nf < 8; nf++) {
            L[nf][0] = expf(L[nf][0] - mn0);
            L[nf][1] = expf(L[nf][1] - mn0);
            L[nf][2] = expf(L[nf][2] - mn1);
            L[nf][3] = expf(L[nf][3] - mn1);
            s0 += L[nf][0] + L[nf][1];
            s1 += L[nf][2] + L[nf][3];
        }
        s0 += __shfl_xor_sync(0xffffffffu, s0, 1);
        s0 += __shfl_xor_sync(0xffffffffu, s0, 2);
        s1 += __shfl_xor_sync(0xffffffffu, s1, 1);
        s1 += __shfl_xor_sync(0xffffffffu, s1, 2);
        l0 = l0 * cor0 + s0; l1 = l1 * cor1 + s1;
        m0 = mn0; m1 = mn1;
        #pragma unroll
        for (int nf = 0; nf < 8; nf++) {
            O[nf][0] *= cor0; O[nf][1] *= cor0;
            O[nf][2] *= cor1; O[nf][3] *= cor1;
        }
        // P -> bf16 A-fragments
        uint32_t pa[4][4];
        #pragma unroll
        for (int kk = 0; kk < 4; kk++) {
            pa[kk][0] = pack_bf162(L[2*kk][0],   L[2*kk][1]);
            pa[kk][1] = pack_bf162(L[2*kk][2],   L[2*kk][3]);
            pa[kk][2] = pack_bf162(L[2*kk+1][0], L[2*kk+1][1]);
            pa[kk][3] = pack_bf162(L[2*kk+1][2], L[2*kk+1][3]);
        }
        #pragma unroll
        for (int nf = 0; nf < 8; nf++) {
            int nb = nf * 8 + qd;
            #pragma unroll
            for (int kk = 0; kk < 4; kk++) {
                uint32_t b0 = *(const uint32_t*)&Vt[nb][kk * 16 + c2];
                uint32_t b1 = *(const uint32_t*)&Vt[nb][kk * 16 + c2 + 8];
                mma16816(O[nf], pa[kk], b0, b1);
            }
        }
    }
    float i0 = 1.f / l0, i1 = 1.f / l1;
    int b = bh >> 4, hh = bh & 15;
    int r0 = qt * 128 + w * 16 + qd;
    #pragma unroll
    for (int nf = 0; nf < 8; nf++) {
        size_t base0 = ((size_t)b * Sc + r0)     * Hc + hh * 64 + nf * 8 + c2;
        size_t base1 = ((size_t)b * Sc + r0 + 8) * Hc + hh * 64 + nf * 8 + c2;
        *(uint32_t*)&g_y[base0] = pack_bf162(O[nf][0] * i0, O[nf][1] * i0);
        *(uint32_t*)&g_y[base1] = pack_bf162(O[nf][2] * i1, O[nf][3] * i1);
    }
    // max softmax weight per row = 1/l (running m ends as the global max)
    float contrib = ((lane & 3) == 0) ? (i0 + i1) : 0.f;
    float t = block_sum256(contrib, sm8);
    if (tid == 0) atomicAdd(&g_acc[1], t);
}

// ---------------- finalize scalars ----------------
__global__ void k_fin(float* __restrict__ out, int out_size) {
    __shared__ float sm8[8];
    int tid = threadIdx.x;
    float dsum = 0.f; int zc = 0, pc = 0;
    for (int j = tid; j < MLPc; j += 256) {
        int c = g_pos[j];
        float fp = c * (1.f / 8192.f);
        dsum += fabsf(fp - 0.5f);
        zc += (c == 0);
        pc += (c == 8192);
    }
    float d = block_sum256(dsum, sm8);
    float z = block_sum256((float)zc, sm8);
    float p = block_sum256((float)pc, sm8);
    if (tid == 0 && out_size != MROWS * Hc) {
        float* o = out + (out_size - 7);
        o[0] = d * (1.f / 4096.f);
        o[1] = z * (1.f / 4096.f);
        o[2] = p * (1.f / 4096.f);
        o[3] = g_acc[1] * (1.f / 131072.f);
        o[4] = sqrtf(g_acc[2] / g_acc[0]);
        o[5] = sqrtf(g_acc[5] / g_acc[3]);
        o[6] = sqrtf(g_acc[4] / (8192.f * 4096.f));
    }
}

// ---------------- launch ----------------
extern "C" void kernel_launch(void* const* d_in, const int* in_sizes, int n_in,
                              void* d_out, int out_size) {
    const float* x      = (const float*)d_in[0];
    const float* c      = (const float*)d_in[1];
    const float* w_cond = (const float*)d_in[2];
    const float* w_qkv  = (const float*)d_in[3];
    const float* w_attn = (const float*)d_in[4];
    const float* w_mlp1 = (const float*)d_in[5];
    const float* w_mlp2 = (const float*)d_in[6];
    float* out = (float*)d_out;

    k_zero<<<16, 256>>>();
    k_conv<<<6144, 512>>>(w_qkv,  0, Hc * 3 * Hc);
    k_conv<<<2048, 512>>>(w_attn, 1, Hc * Hc);
    k_conv<<<8192, 512>>>(w_mlp1, 2, Hc * MLPc);
    k_conv<<<8192, 512>>>(w_mlp2, 3, MLPc * Hc);
    k_cond<<<24, 256>>>(c, w_cond);
    k_ln1<<<MROWS, 256>>>(x);
    k_qkv<<<dim3(24, 64), 256>>>();
    k_attn<<<dim3(8, Bc * NHc), 256>>>();
    k_attnout<<<dim3(8, 64), 256>>>(x);
    k_ln2<<<MROWS, 256>>>();
    k_mlp1<<<dim3(32, 64), 256>>>();
    k_mlp2<<<dim3(8, 64), 256>>>(out);
    k_fin<<<1, 256>>>(out, out_size);
}

// round 7
// speedup vs baseline: 2.4665x; 2.4665x over previous
#include <cuda_runtime.h>
#include <cuda_bf16.h>
#include <stdint.h>
#include <math.h>

typedef __nv_bfloat16 bf16;

#define Bc   8
#define Sc   1024
#define Hc   1024
#define NHc  16
#define DHc  64
#define MLPc 4096
#define MROWS (Bc*Sc)   // 8192

// ---------------- device scratch ----------------
__device__ bf16  g_wqT[3*Hc*Hc];         // [3072,1024] (N,K)
__device__ bf16  g_woT[Hc*Hc];           // [1024,1024]
__device__ bf16  g_w1T[(size_t)MLPc*Hc]; // [4096,1024]
__device__ bf16  g_w2T[(size_t)Hc*MLPc]; // [1024,4096]
__device__ float g_cm[Bc*6*Hc];
__device__ bf16  g_xmod[MROWS*Hc];
__device__ bf16  g_q[Bc*NHc*Sc*DHc];
__device__ bf16  g_k[Bc*NHc*Sc*DHc];
__device__ bf16  g_v[Bc*NHc*Sc*DHc];
__device__ bf16  g_y[MROWS*Hc];
__device__ float g_xres[MROWS*Hc];
__device__ bf16  g_h[(size_t)MROWS*MLPc];
__device__ float g_acc[8];
__device__ int   g_pos[MLPc];

// ---------------- low-level helpers ----------------
__device__ __forceinline__ uint32_t smem_u32(const void* p) {
    uint32_t a;
    asm("{ .reg .u64 t; cvta.to.shared.u64 t, %1; cvt.u32.u64 %0, t; }" : "=r"(a) : "l"(p));
    return a;
}
__device__ __forceinline__ void cp_async16(uint32_t s, const void* g) {
    asm volatile("cp.async.cg.shared.global [%0], [%1], 16;" :: "r"(s), "l"(g));
}
#define CP_COMMIT asm volatile("cp.async.commit_group;" ::: "memory")
#define CP_WAIT1  asm volatile("cp.async.wait_group 1;" ::: "memory")

__device__ __forceinline__ uint32_t sw_addr(uint32_t base, int row, int chunk) {
    return base + row * 128 + (((chunk) ^ (row & 7)) << 4);
}
__device__ __forceinline__ void ldsm4(uint32_t r[4], uint32_t a) {
    asm volatile("ldmatrix.sync.aligned.m8n8.x4.shared.b16 {%0,%1,%2,%3}, [%4];"
                 : "=r"(r[0]), "=r"(r[1]), "=r"(r[2]), "=r"(r[3]) : "r"(a));
}
__device__ __forceinline__ void mma16816(float c[4], const uint32_t a[4],
                                         uint32_t b0, uint32_t b1) {
    asm volatile(
        "mma.sync.aligned.m16n8k16.row.col.f32.bf16.bf16.f32 "
        "{%0,%1,%2,%3},{%4,%5,%6,%7},{%8,%9},{%0,%1,%2,%3};\n"
        : "+f"(c[0]), "+f"(c[1]), "+f"(c[2]), "+f"(c[3])
        : "r"(a[0]), "r"(a[1]), "r"(a[2]), "r"(a[3]), "r"(b0), "r"(b1));
}
__device__ __forceinline__ uint32_t pack_bf162(float x, float y) {
    __nv_bfloat162 h = __floats2bfloat162_rn(x, y);
    return *(uint32_t*)&h;
}
__device__ __forceinline__ float block_sum256(float v, float* sm8) {
    #pragma unroll
    for (int o = 16; o > 0; o >>= 1) v += __shfl_xor_sync(0xffffffffu, v, o);
    __syncthreads();
    if ((threadIdx.x & 31) == 0) sm8[threadIdx.x >> 5] = v;
    __syncthreads();
    float r = 0.f;
    #pragma unroll
    for (int i = 0; i < 8; i++) r += sm8[i];
    return r;
}

// ---------------- small kernels ----------------
__global__ void k_zero() {
    int i = blockIdx.x * 256 + threadIdx.x;
    if (i < MLPc) g_pos[i] = 0;
    if (i < 8)    g_acc[i] = 0.f;
}

// tiled transpose+convert: src[R,C] f32 -> dst[C,R] bf16.
// DESTINATION SELECTED IN DEVICE CODE (sel) — passing a __device__ symbol as a
// host-side kernel arg passes the host shadow address (ATS makes the write
// silently land in host RAM; device buffer stays zero). Root cause of R3-R6.
__global__ void k_trans(const float* __restrict__ src, int sel, int R, int C) {
    bf16* dst = (sel == 0) ? g_wqT : (sel == 1) ? g_woT : (sel == 2) ? g_w1T : g_w2T;
    __shared__ float t[32][33];
    int cb = blockIdx.x * 32, rb = blockIdx.y * 32;
    int tx = threadIdx.x & 31, ty = threadIdx.x >> 5;
    #pragma unroll
    for (int i = 0; i < 32; i += 8)
        t[ty + i][tx] = src[(size_t)(rb + ty + i) * C + cb + tx];
    __syncthreads();
    #pragma unroll
    for (int i = 0; i < 32; i += 8)
        dst[(size_t)(cb + ty + i) * R + rb + tx] = __float2bfloat16(t[tx][ty + i]);
}

// cm[b][j] = sum_k silu(c[b][k]) * w_cond[k][j]  (round-1 proven)
__global__ void k_cond(const float* __restrict__ c, const float* __restrict__ w) {
    __shared__ float ssil[Bc * Hc];     // 32 KB
    int tid = threadIdx.x;
    for (int i = tid; i < Bc * Hc; i += 256) {
        float v = c[i];
        ssil[i] = v / (1.f + expf(-v));
    }
    __syncthreads();
    int j = blockIdx.x * 256 + tid;
    float acc[Bc];
    #pragma unroll
    for (int b = 0; b < Bc; b++) acc[b] = 0.f;
    for (int k = 0; k < Hc; k++) {
        float wv = w[(size_t)k * (6 * Hc) + j];
        #pragma unroll
        for (int b = 0; b < Bc; b++) acc[b] += ssil[b * Hc + k] * wv;
    }
    #pragma unroll
    for (int b = 0; b < Bc; b++) g_cm[b * 6 * Hc + j] = acc[b];
}

// LayerNorm (fp32 stats, bf16 output) + adaLN modulate -> bf16
__device__ __forceinline__ void ln_impl(const float* __restrict__ xin,
                                        bf16* __restrict__ xout,
                                        int so, int sco, float* ssq) {
    __shared__ float sm8[8];
    int row = blockIdx.x;
    int b = row >> 10;
    int tid = threadIdx.x;
    const float* xr = xin + (size_t)row * Hc;
    float v[4];
    #pragma unroll
    for (int i = 0; i < 4; i++) v[i] = xr[tid + i * 256];
    float s = v[0] + v[1] + v[2] + v[3];
    float mean = block_sum256(s, sm8) * (1.f / 1024.f);
    float s2 = 0.f;
    #pragma unroll
    for (int i = 0; i < 4; i++) { float d = v[i] - mean; s2 += d * d; }
    float var = block_sum256(s2, sm8) * (1.f / 1024.f);
    float rstd = rsqrtf(var + 1e-6f);
    const float* cmb = g_cm + b * 6 * Hc;
    #pragma unroll
    for (int i = 0; i < 4; i++) {
        int col = tid + i * 256;
        float lnv = __bfloat162float(__float2bfloat16((v[i] - mean) * rstd));
        float xm = lnv * cmb[sco * Hc + col] + cmb[so * Hc + col];
        xout[(size_t)row * Hc + col] = __float2bfloat16(xm);
    }
    if (ssq) {
        float q = v[0]*v[0] + v[1]*v[1] + v[2]*v[2] + v[3]*v[3];
        float t = block_sum256(q, sm8);
        if (tid == 0) atomicAdd(ssq, t);
    }
}
__global__ void k_ln1(const float* __restrict__ x) { ln_impl(x, g_xmod, 0, 1, &g_acc[0]); }
__global__ void k_ln2()                             { ln_impl(g_xres, g_xmod, 3, 4, &g_acc[3]); }

// ---------------- pipelined mma.sync GEMM core ----------------
// BM=128, BN=128, BK=64, 3 cp.async stages, 256 threads (8 warps: 4m x 2n).
#define STG 32768
#define SMEM_G 100352

__device__ __forceinline__ void issue_stage(const bf16* __restrict__ A,
                                            const bf16* __restrict__ Bm, int K,
                                            int tileM, int tileN, uint32_t sbase, int kt) {
    const int tid = threadIdx.x;
    #pragma unroll
    for (int t = 0; t < 4; t++) {
        int ch = tid + t * 256;
        int row = ch >> 3, c = ch & 7;
        cp_async16(sw_addr(sbase, row, c), A + (size_t)(tileM + row) * K + kt + c * 8);
    }
    #pragma unroll
    for (int t = 0; t < 4; t++) {
        int ch = tid + t * 256;
        int row = ch >> 3, c = ch & 7;
        cp_async16(sw_addr(sbase + 16384, row, c), Bm + (size_t)(tileN + row) * K + kt + c * 8);
    }
}

__device__ __forceinline__ void gemm_core(const bf16* __restrict__ A,
                                          const bf16* __restrict__ Bm, int K,
                                          int tileM, int tileN, char* dsm,
                                          float acc[2][8][4]) {
    uint32_t sb = smem_u32(dsm);
    const int tid = threadIdx.x, lane = tid & 31, warp = tid >> 5;
    const int wm = warp & 3, wn = warp >> 2;
    const int g = lane >> 3, lr = lane & 7;
    #pragma unroll
    for (int mf = 0; mf < 2; mf++)
        #pragma unroll
        for (int nf = 0; nf < 8; nf++)
            #pragma unroll
            for (int i = 0; i < 4; i++) acc[mf][nf][i] = 0.f;

    const int nk = K >> 6;
    issue_stage(A, Bm, K, tileM, tileN, sb, 0);          CP_COMMIT;
    issue_stage(A, Bm, K, tileM, tileN, sb + STG, 64);   CP_COMMIT;

    for (int kc = 0; kc < nk; kc++) {
        CP_WAIT1;
        __syncthreads();
        uint32_t as = sb + (kc % 3) * STG;
        uint32_t bs = as + 16384;
        #pragma unroll
        for (int kk = 0; kk < 4; kk++) {
            uint32_t a0[4], a1[4];
            ldsm4(a0, sw_addr(as, wm * 32 + (g & 1) * 8 + lr,      kk * 2 + (g >> 1)));
            ldsm4(a1, sw_addr(as, wm * 32 + 16 + (g & 1) * 8 + lr, kk * 2 + (g >> 1)));
            #pragma unroll
            for (int p = 0; p < 4; p++) {
                uint32_t b[4];
                ldsm4(b, sw_addr(bs, wn * 64 + p * 16 + (g & 1) * 8 + lr, kk * 2 + (g >> 1)));
                mma16816(acc[0][2*p],   a0, b[0], b[2]);
                mma16816(acc[0][2*p+1], a0, b[1], b[3]);
                mma16816(acc[1][2*p],   a1, b[0], b[2]);
                mma16816(acc[1][2*p+1], a1, b[1], b[3]);
            }
        }
        if (kc + 2 < nk)
            issue_stage(A, Bm, K, tileM, tileN, sb + ((kc + 2) % 3) * STG, (kc + 2) * 64);
        CP_COMMIT;
    }
    __syncthreads();
}

#define GEMM_EPI_COORDS                                             \
    const int lane = threadIdx.x & 31, warp = threadIdx.x >> 5;     \
    const int wm = warp & 3, wn = warp >> 2;                        \
    const int qd = lane >> 2, c2 = (lane & 3) << 1;                 \
    const int tileM = blockIdx.y * 128, tileN = blockIdx.x * 128;

// qkv: split cols (k,q,v), scale q by 1/8, scatter to [b,h,s,d]
__global__ void __launch_bounds__(256) k_qkv() {
    extern __shared__ char dsm[];
    float acc[2][8][4];
    gemm_core(g_xmod, g_wqT, Hc, blockIdx.y * 128, blockIdx.x * 128, dsm, acc);
    GEMM_EPI_COORDS
    #pragma unroll
    for (int mf = 0; mf < 2; mf++)
        #pragma unroll
        for (int nf = 0; nf < 8; nf++)
            #pragma unroll
            for (int i = 0; i < 4; i++) {
                int r  = tileM + wm * 32 + mf * 16 + qd + ((i >> 1) << 3);
                int cc = tileN + wn * 64 + nf * 8 + c2 + (i & 1);
                int t = cc >> 10, rem = cc & 1023;
                int hh = rem >> 6, d = rem & 63;
                int b = r >> 10, s = r & 1023;
                float val = acc[mf][nf][i];
                size_t o = (((size_t)(b * NHc + hh)) * Sc + s) * DHc + d;
                if (t == 0)      g_k[o] = __float2bfloat16(val);
                else if (t == 1) g_q[o] = __float2bfloat16(val * 0.125f);
                else             g_v[o] = __float2bfloat16(val);
            }
}

// attn-out: x_res = x + gate_msa*acc ; sumsq_attn
__global__ void __launch_bounds__(256) k_attnout(const float* __restrict__ x_in) {
    extern __shared__ char dsm[];
    float* sm8 = (float*)(dsm + 98304);
    float acc[2][8][4];
    gemm_core(g_y, g_woT, Hc, blockIdx.y * 128, blockIdx.x * 128, dsm, acc);
    GEMM_EPI_COORDS
    float ss = 0.f;
    #pragma unroll
    for (int mf = 0; mf < 2; mf++)
        #pragma unroll
        for (int nf = 0; nf < 8; nf++)
            #pragma unroll
            for (int i = 0; i < 4; i++) {
                int r  = tileM + wm * 32 + mf * 16 + qd + ((i >> 1) << 3);
                int cc = tileN + wn * 64 + nf * 8 + c2 + (i & 1);
                int b = r >> 10;
                float gg = g_cm[b * 6 * Hc + 2 * Hc + cc];
                float a = gg * acc[mf][nf][i];
                size_t idx = (size_t)r * Hc + cc;
                g_xres[idx] = x_in[idx] + a;
                ss += a * a;
            }
    float t = block_sum256(ss, sm8);
    if (threadIdx.x == 0) atomicAdd(&g_acc[2], t);
}

// mlp1: positive counts, sumsq_relu, tanh-gelu -> bf16 h
__global__ void __launch_bounds__(256) k_mlp1() {
    extern __shared__ char dsm[];
    float* sm8 = (float*)(dsm + 98304);
    int* scnt = (int*)(dsm + 98368);
    if (threadIdx.x < 128) scnt[threadIdx.x] = 0;
    float acc[2][8][4];
    gemm_core(g_xmod, g_w1T, Hc, blockIdx.y * 128, blockIdx.x * 128, dsm, acc);
    GEMM_EPI_COORDS
    float ss = 0.f;
    #pragma unroll
    for (int nf = 0; nf < 8; nf++) {
        int cnt0 = 0, cnt1 = 0;
        #pragma unroll
        for (int mf = 0; mf < 2; mf++)
            #pragma unroll
            for (int i = 0; i < 4; i++) {
                float t = acc[mf][nf][i];
                ss += t * t;
                if (i & 1) cnt1 += (t > 0.f); else cnt0 += (t > 0.f);
                float u = 0.7978845608028654f * (t + 0.044715f * t * t * t);
                float gl = 0.5f * t * (1.f + tanhf(u));
                int r  = tileM + wm * 32 + mf * 16 + qd + ((i >> 1) << 3);
                int cc = tileN + wn * 64 + nf * 8 + c2 + (i & 1);
                g_h[(size_t)r * MLPc + cc] = __float2bfloat16(gl);
            }
        atomicAdd(&scnt[wn * 64 + nf * 8 + c2], cnt0);
        atomicAdd(&scnt[wn * 64 + nf * 8 + c2 + 1], cnt1);
    }
    __syncthreads();
    if (threadIdx.x < 128) atomicAdd(&g_pos[tileN + threadIdx.x], scnt[threadIdx.x]);
    float t = block_sum256(ss, sm8);
    if (threadIdx.x == 0) atomicAdd(&g_acc[4], t);
}

// mlp2: out = x_res + gate_mlp*acc ; sumsq_mlp
__global__ void __launch_bounds__(256) k_mlp2(float* __restrict__ out) {
    extern __shared__ char dsm[];
    float* sm8 = (float*)(dsm + 98304);
    float acc[2][8][4];
    gemm_core(g_h, g_w2T, MLPc, blockIdx.y * 128, blockIdx.x * 128, dsm, acc);
    GEMM_EPI_COORDS
    float ss = 0.f;
    #pragma unroll
    for (int mf = 0; mf < 2; mf++)
        #pragma unroll
        for (int nf = 0; nf < 8; nf++)
            #pragma unroll
            for (int i = 0; i < 4; i++) {
                int r  = tileM + wm * 32 + mf * 16 + qd + ((i >> 1) << 3);
                int cc = tileN + wn * 64 + nf * 8 + c2 + (i & 1);
                int b = r >> 10;
                float gg = g_cm[b * 6 * Hc + 5 * Hc + cc];
                float m = gg * acc[mf][nf][i];
                size_t idx = (size_t)r * Hc + cc;
                out[idx] = g_xres[idx] + m;
                ss += m * m;
            }
    float t = block_sum256(ss, sm8);
    if (threadIdx.x == 0) atomicAdd(&g_acc[5], t);
}

// ---------------- flash attention (round-1 proven) ----------------
__global__ void k_attn() {
    __shared__ bf16 Qs[128][72], Ks[64][72], Vt[64][72];
    __shared__ float sm8[8];
    const int tid = threadIdx.x, lane = tid & 31, w = tid >> 5;
    const int qd = lane >> 2, c2 = (lane & 3) << 1;
    const int bh = blockIdx.y, qt = blockIdx.x;

    const bf16* Qg = g_q + ((size_t)bh * Sc + qt * 128) * DHc;
    #pragma unroll
    for (int t = 0; t < 4; t++) {
        int ch = tid + t * 256;
        int row = ch >> 3, dc = ch & 7;
        *(uint4*)&Qs[row][dc * 8] = *(const uint4*)(Qg + row * DHc + dc * 8);
    }
    __syncthreads();

    uint32_t qa[4][4];
    {
        int ra = w * 16 + qd;
        #pragma unroll
        for (int kk = 0; kk < 4; kk++) {
            int kb = kk * 16;
            qa[kk][0] = *(const uint32_t*)&Qs[ra][kb + c2];
            qa[kk][1] = *(const uint32_t*)&Qs[ra + 8][kb + c2];
            qa[kk][2] = *(const uint32_t*)&Qs[ra][kb + c2 + 8];
            qa[kk][3] = *(const uint32_t*)&Qs[ra + 8][kb + c2 + 8];
        }
    }
    float O[8][4];
    #pragma unroll
    for (int nf = 0; nf < 8; nf++)
        #pragma unroll
        for (int i = 0; i < 4; i++) O[nf][i] = 0.f;
    float m0 = -1e30f, m1 = -1e30f, l0 = 0.f, l1 = 0.f;

    for (int kt = 0; kt < Sc / 64; kt++) {
        __syncthreads();
        const bf16* Kg = g_k + ((size_t)bh * Sc + kt * 64) * DHc;
        const bf16* Vg = g_v + ((size_t)bh * Sc + kt * 64) * DHc;
        #pragma unroll
        for (int t = 0; t < 2; t++) {
            int ch = tid + t * 256;
            int row = ch >> 3, dc = ch & 7;
            *(uint4*)&Ks[row][dc * 8] = *(const uint4*)(Kg + row * DHc + dc * 8);
            uint4 u = *(const uint4*)(Vg + row * DHc + dc * 8);
            const bf16* pv = (const bf16*)&u;
            #pragma unroll
            for (int i = 0; i < 8; i++) Vt[dc * 8 + i][row] = pv[i];
        }
        __syncthreads();

        float L[8][4];
        #pragma unroll
        for (int nf = 0; nf < 8; nf++) {
            L[nf][0] = L[nf][1] = L[nf][2] = L[nf][3] = 0.f;
            int nb = nf * 8 + qd;
            #pragma unroll
            for (int kk = 0; kk < 4; kk++) {
                uint32_t b0 = *(const uint32_t*)&Ks[nb][kk * 16 + c2];
                uint32_t b1 = *(const uint32_t*)&Ks[nb][kk * 16 + c2 + 8];
                mma16816(L[nf], qa[kk], b0, b1);
            }
        }
        float tm0 = -1e30f, tm1 = -1e30f;
        #pragma unroll
        for (int nf = 0; nf < 8; nf++) {
            tm0 = fmaxf(tm0, fmaxf(L[nf][0], L[nf][1]));
            tm1 = fmaxf(tm1, fmaxf(L[nf][2], L[nf][3]));
        }
        tm0 = fmaxf(tm0, __shfl_xor_sync(0xffffffffu, tm0, 1));
        tm0 = fmaxf(tm0, __shfl_xor_sync(0xffffffffu, tm0, 2));
        tm1 = fmaxf(tm1, __shfl_xor_sync(0xffffffffu, tm1, 1));
        tm1 = fmaxf(tm1, __shfl_xor_sync(0xffffffffu, tm1, 2));
        float mn0 = fmaxf(m0, tm0), mn1 = fmaxf(m1, tm1);
        float cor0 = expf(m0 - mn0), cor1 = expf(m1 - mn1);
        float s0 = 0.f, s1 = 0.f;
        #pragma unroll
        for (int nf = 0; nf < 8; nf++) {
            L[nf][0] = expf(L[nf][0] - mn0);
            L[nf][1] = expf(L[nf][1] - mn0);
            L[nf][2] = expf(L[nf][2] - mn1);
            L[nf][3] = expf(L[nf][3] - mn1);
            s0 += L[nf][0] + L[nf][1];
            s1 += L[nf][2] + L[nf][3];
        }
        s0 += __shfl_xor_sync(0xffffffffu, s0, 1);
        s0 += __shfl_xor_sync(0xffffffffu, s0, 2);
        s1 += __shfl_xor_sync(0xffffffffu, s1, 1);
        s1 += __shfl_xor_sync(0xffffffffu, s1, 2);
        l0 = l0 * cor0 + s0; l1 = l1 * cor1 + s1;
        m0 = mn0; m1 = mn1;
        #pragma unroll
        for (int nf = 0; nf < 8; nf++) {
            O[nf][0] *= cor0; O[nf][1] *= cor0;
            O[nf][2] *= cor1; O[nf][3] *= cor1;
        }
        uint32_t pa[4][4];
        #pragma unroll
        for (int kk = 0; kk < 4; kk++) {
            pa[kk][0] = pack_bf162(L[2*kk][0],   L[2*kk][1]);
            pa[kk][1] = pack_bf162(L[2*kk][2],   L[2*kk][3]);
            pa[kk][2] = pack_bf162(L[2*kk+1][0], L[2*kk+1][1]);
            pa[kk][3] = pack_bf162(L[2*kk+1][2], L[2*kk+1][3]);
        }
        #pragma unroll
        for (int nf = 0; nf < 8; nf++) {
            int nb = nf * 8 + qd;
            #pragma unroll
            for (int kk = 0; kk < 4; kk++) {
                uint32_t b0 = *(const uint32_t*)&Vt[nb][kk * 16 + c2];
                uint32_t b1 = *(const uint32_t*)&Vt[nb][kk * 16 + c2 + 8];
                mma16816(O[nf], pa[kk], b0, b1);
            }
        }
    }
    float i0 = 1.f / l0, i1 = 1.f / l1;
    int b = bh >> 4, hh = bh & 15;
    int r0 = qt * 128 + w * 16 + qd;
    #pragma unroll
    for (int nf = 0; nf < 8; nf++) {
        size_t base0 = ((size_t)b * Sc + r0)     * Hc + hh * 64 + nf * 8 + c2;
        size_t base1 = ((size_t)b * Sc + r0 + 8) * Hc + hh * 64 + nf * 8 + c2;
        *(uint32_t*)&g_y[base0] = pack_bf162(O[nf][0] * i0, O[nf][1] * i0);
        *(uint32_t*)&g_y[base1] = pack_bf162(O[nf][2] * i1, O[nf][3] * i1);
    }
    float contrib = ((lane & 3) == 0) ? (i0 + i1) : 0.f;
    float t = block_sum256(contrib, sm8);
    if (tid == 0) atomicAdd(&g_acc[1], t);
}

// ---------------- finalize scalars ----------------
__global__ void k_fin(float* __restrict__ out, int out_size) {
    __shared__ float sm8[8];
    int tid = threadIdx.x;
    float dsum = 0.f; int zc = 0, pc = 0;
    for (int j = tid; j < MLPc; j += 256) {
        int c = g_pos[j];
        float fp = c * (1.f / 8192.f);
        dsum += fabsf(fp - 0.5f);
        zc += (c == 0);
        pc += (c == 8192);
    }
    float d = block_sum256(dsum, sm8);
    float z = block_sum256((float)zc, sm8);
    float p = block_sum256((float)pc, sm8);
    if (tid == 0 && out_size != MROWS * Hc) {
        float* o = out + (out_size - 7);
        o[0] = d * (1.f / 4096.f);
        o[1] = z * (1.f / 4096.f);
        o[2] = p * (1.f / 4096.f);
        o[3] = g_acc[1] * (1.f / 131072.f);
        o[4] = sqrtf(g_acc[2] / g_acc[0]);
        o[5] = sqrtf(g_acc[5] / g_acc[3]);
        o[6] = sqrtf(g_acc[4] / (8192.f * 4096.f));
    }
}

// ---------------- launch ----------------
extern "C" void kernel_launch(void* const* d_in, const int* in_sizes, int n_in,
                              void* d_out, int out_size) {
    const float* x      = (const float*)d_in[0];
    const float* c      = (const float*)d_in[1];
    const float* w_cond = (const float*)d_in[2];
    const float* w_qkv  = (const float*)d_in[3];
    const float* w_attn = (const float*)d_in[4];
    const float* w_mlp1 = (const float*)d_in[5];
    const float* w_mlp2 = (const float*)d_in[6];
    float* out = (float*)d_out;

    cudaFuncSetAttribute(k_qkv,     cudaFuncAttributeMaxDynamicSharedMemorySize, SMEM_G);
    cudaFuncSetAttribute(k_attnout, cudaFuncAttributeMaxDynamicSharedMemorySize, SMEM_G);
    cudaFuncSetAttribute(k_mlp1,    cudaFuncAttributeMaxDynamicSharedMemorySize, SMEM_G);
    cudaFuncSetAttribute(k_mlp2,    cudaFuncAttributeMaxDynamicSharedMemorySize, SMEM_G);

    k_zero<<<16, 256>>>();
    k_trans<<<dim3(96, 32),  256>>>(w_qkv,  0, Hc,   3*Hc);
    k_trans<<<dim3(32, 32),  256>>>(w_attn, 1, Hc,   Hc);
    k_trans<<<dim3(128, 32), 256>>>(w_mlp1, 2, Hc,   MLPc);
    k_trans<<<dim3(32, 128), 256>>>(w_mlp2, 3, MLPc, Hc);
    k_cond<<<24, 256>>>(c, w_cond);
    k_ln1<<<MROWS, 256>>>(x);
    k_qkv<<<dim3(24, 64), 256, SMEM_G>>>();
    k_attn<<<dim3(8, Bc * NHc), 256>>>();
    k_attnout<<<dim3(8, 64), 256, SMEM_G>>>(x);
    k_ln2<<<MROWS, 256>>>();
    k_mlp1<<<dim3(32, 64), 256, SMEM_G>>>();
    k_mlp2<<<dim3(8, 64), 256, SMEM_G>>>(out);
    k_fin<<<1, 256>>>(out, out_size);
}

// round 8
// speedup vs baseline: 2.9722x; 1.2050x over previous
#include <cuda_runtime.h>
#include <cuda_bf16.h>
#include <stdint.h>
#include <math.h>

typedef __nv_bfloat16 bf16;

#define Bc   8
#define Sc   1024
#define Hc   1024
#define NHc  16
#define DHc  64
#define MLPc 4096
#define MROWS (Bc*Sc)   // 8192

// ---------------- device scratch ----------------
__device__ bf16  g_wqT[3*Hc*Hc];         // [3072,1024] (N,K)
__device__ bf16  g_woT[Hc*Hc];           // [1024,1024]
__device__ bf16  g_w1T[(size_t)MLPc*Hc]; // [4096,1024]
__device__ bf16  g_w2T[(size_t)Hc*MLPc]; // [1024,4096]
__device__ float g_cm[Bc*6*Hc];
__device__ bf16  g_xmod[MROWS*Hc];
__device__ bf16  g_q[Bc*NHc*Sc*DHc];
__device__ bf16  g_k[Bc*NHc*Sc*DHc];
__device__ bf16  g_v[Bc*NHc*Sc*DHc];
__device__ bf16  g_y[MROWS*Hc];
__device__ float g_xres[MROWS*Hc];
__device__ bf16  g_h[(size_t)MROWS*MLPc];
__device__ float g_acc[8];
__device__ int   g_pos[MLPc];

// ---------------- low-level helpers ----------------
__device__ __forceinline__ uint32_t smem_u32(const void* p) {
    uint32_t a;
    asm("{ .reg .u64 t; cvta.to.shared.u64 t, %1; cvt.u32.u64 %0, t; }" : "=r"(a) : "l"(p));
    return a;
}
__device__ __forceinline__ void cp_async16(uint32_t s, const void* g) {
    asm volatile("cp.async.cg.shared.global [%0], [%1], 16;" :: "r"(s), "l"(g));
}
#define CP_COMMIT asm volatile("cp.async.commit_group;" ::: "memory")
#define CP_WAIT1  asm volatile("cp.async.wait_group 1;" ::: "memory")
#define CP_WAIT0  asm volatile("cp.async.wait_group 0;" ::: "memory")

__device__ __forceinline__ uint32_t sw_addr(uint32_t base, int row, int chunk) {
    return base + row * 128 + (((chunk) ^ (row & 7)) << 4);
}
__device__ __forceinline__ void ldsm4(uint32_t r[4], uint32_t a) {
    asm volatile("ldmatrix.sync.aligned.m8n8.x4.shared.b16 {%0,%1,%2,%3}, [%4];"
                 : "=r"(r[0]), "=r"(r[1]), "=r"(r[2]), "=r"(r[3]) : "r"(a));
}
__device__ __forceinline__ void ldsm4t(uint32_t r[4], uint32_t a) {
    asm volatile("ldmatrix.sync.aligned.m8n8.x4.trans.shared.b16 {%0,%1,%2,%3}, [%4];"
                 : "=r"(r[0]), "=r"(r[1]), "=r"(r[2]), "=r"(r[3]) : "r"(a));
}
__device__ __forceinline__ void mma16816(float c[4], const uint32_t a[4],
                                         uint32_t b0, uint32_t b1) {
    asm volatile(
        "mma.sync.aligned.m16n8k16.row.col.f32.bf16.bf16.f32 "
        "{%0,%1,%2,%3},{%4,%5,%6,%7},{%8,%9},{%0,%1,%2,%3};\n"
        : "+f"(c[0]), "+f"(c[1]), "+f"(c[2]), "+f"(c[3])
        : "r"(a[0]), "r"(a[1]), "r"(a[2]), "r"(a[3]), "r"(b0), "r"(b1));
}
__device__ __forceinline__ uint32_t pack_bf162(float x, float y) {
    __nv_bfloat162 h = __floats2bfloat162_rn(x, y);
    return *(uint32_t*)&h;
}
__device__ __forceinline__ float block_sum256(float v, float* sm8) {
    #pragma unroll
    for (int o = 16; o > 0; o >>= 1) v += __shfl_xor_sync(0xffffffffu, v, o);
    __syncthreads();
    if ((threadIdx.x & 31) == 0) sm8[threadIdx.x >> 5] = v;
    __syncthreads();
    float r = 0.f;
    #pragma unroll
    for (int i = 0; i < 8; i++) r += sm8[i];
    return r;
}

// ---------------- small kernels ----------------
__global__ void k_zero() {
    int i = blockIdx.x * 256 + threadIdx.x;
    if (i < MLPc) g_pos[i] = 0;
    if (i < 8)    g_acc[i] = 0.f;
}

// tiled transpose+convert: src[R,C] f32 -> dst[C,R] bf16.
// Destination selected in device code (sel): passing a __device__ symbol as a
// host-side kernel arg passes the host shadow address (ATS swallows the write).
__global__ void k_trans(const float* __restrict__ src, int sel, int R, int C) {
    bf16* dst = (sel == 0) ? g_wqT : (sel == 1) ? g_woT : (sel == 2) ? g_w1T : g_w2T;
    __shared__ float t[32][33];
    int cb = blockIdx.x * 32, rb = blockIdx.y * 32;
    int tx = threadIdx.x & 31, ty = threadIdx.x >> 5;
    #pragma unroll
    for (int i = 0; i < 32; i += 8)
        t[ty + i][tx] = src[(size_t)(rb + ty + i) * C + cb + tx];
    __syncthreads();
    #pragma unroll
    for (int i = 0; i < 32; i += 8)
        dst[(size_t)(cb + ty + i) * R + rb + tx] = __float2bfloat16(t[tx][ty + i]);
}

// cm[b][j] = sum_k silu(c[b][k]) * w_cond[k][j]  (round-1 proven)
__global__ void k_cond(const float* __restrict__ c, const float* __restrict__ w) {
    __shared__ float ssil[Bc * Hc];     // 32 KB
    int tid = threadIdx.x;
    for (int i = tid; i < Bc * Hc; i += 256) {
        float v = c[i];
        ssil[i] = v / (1.f + expf(-v));
    }
    __syncthreads();
    int j = blockIdx.x * 256 + tid;
    float acc[Bc];
    #pragma unroll
    for (int b = 0; b < Bc; b++) acc[b] = 0.f;
    for (int k = 0; k < Hc; k++) {
        float wv = w[(size_t)k * (6 * Hc) + j];
        #pragma unroll
        for (int b = 0; b < Bc; b++) acc[b] += ssil[b * Hc + k] * wv;
    }
    #pragma unroll
    for (int b = 0; b < Bc; b++) g_cm[b * 6 * Hc + j] = acc[b];
}

// LayerNorm (fp32 stats, bf16 output) + adaLN modulate -> bf16
__device__ __forceinline__ void ln_impl(const float* __restrict__ xin,
                                        bf16* __restrict__ xout,
                                        int so, int sco, float* ssq) {
    __shared__ float sm8[8];
    int row = blockIdx.x;
    int b = row >> 10;
    int tid = threadIdx.x;
    const float* xr = xin + (size_t)row * Hc;
    float v[4];
    #pragma unroll
    for (int i = 0; i < 4; i++) v[i] = xr[tid + i * 256];
    float s = v[0] + v[1] + v[2] + v[3];
    float mean = block_sum256(s, sm8) * (1.f / 1024.f);
    float s2 = 0.f;
    #pragma unroll
    for (int i = 0; i < 4; i++) { float d = v[i] - mean; s2 += d * d; }
    float var = block_sum256(s2, sm8) * (1.f / 1024.f);
    float rstd = rsqrtf(var + 1e-6f);
    const float* cmb = g_cm + b * 6 * Hc;
    #pragma unroll
    for (int i = 0; i < 4; i++) {
        int col = tid + i * 256;
        float lnv = __bfloat162float(__float2bfloat16((v[i] - mean) * rstd));
        float xm = lnv * cmb[sco * Hc + col] + cmb[so * Hc + col];
        xout[(size_t)row * Hc + col] = __float2bfloat16(xm);
    }
    if (ssq) {
        float q = v[0]*v[0] + v[1]*v[1] + v[2]*v[2] + v[3]*v[3];
        float t = block_sum256(q, sm8);
        if (tid == 0) atomicAdd(ssq, t);
    }
}
__global__ void k_ln1(const float* __restrict__ x) { ln_impl(x, g_xmod, 0, 1, &g_acc[0]); }
__global__ void k_ln2()                             { ln_impl(g_xres, g_xmod, 3, 4, &g_acc[3]); }

// ---------------- pipelined mma.sync GEMM core (validated R7) ----------------
// BM=128, BN=128, BK=64, 3 cp.async stages, 256 threads (8 warps: 4m x 2n).
#define STG 32768
#define SMEM_G 100352

__device__ __forceinline__ void issue_stage(const bf16* __restrict__ A,
                                            const bf16* __restrict__ Bm, int K,
                                            int tileM, int tileN, uint32_t sbase, int kt) {
    const int tid = threadIdx.x;
    #pragma unroll
    for (int t = 0; t < 4; t++) {
        int ch = tid + t * 256;
        int row = ch >> 3, c = ch & 7;
        cp_async16(sw_addr(sbase, row, c), A + (size_t)(tileM + row) * K + kt + c * 8);
    }
    #pragma unroll
    for (int t = 0; t < 4; t++) {
        int ch = tid + t * 256;
        int row = ch >> 3, c = ch & 7;
        cp_async16(sw_addr(sbase + 16384, row, c), Bm + (size_t)(tileN + row) * K + kt + c * 8);
    }
}

__device__ __forceinline__ void gemm_core(const bf16* __restrict__ A,
                                          const bf16* __restrict__ Bm, int K,
                                          int tileM, int tileN, char* dsm,
                                          float acc[2][8][4]) {
    uint32_t sb = smem_u32(dsm);
    const int tid = threadIdx.x, lane = tid & 31, warp = tid >> 5;
    const int wm = warp & 3, wn = warp >> 2;
    const int g = lane >> 3, lr = lane & 7;
    #pragma unroll
    for (int mf = 0; mf < 2; mf++)
        #pragma unroll
        for (int nf = 0; nf < 8; nf++)
            #pragma unroll
            for (int i = 0; i < 4; i++) acc[mf][nf][i] = 0.f;

    const int nk = K >> 6;
    issue_stage(A, Bm, K, tileM, tileN, sb, 0);          CP_COMMIT;
    issue_stage(A, Bm, K, tileM, tileN, sb + STG, 64);   CP_COMMIT;

    for (int kc = 0; kc < nk; kc++) {
        CP_WAIT1;
        __syncthreads();
        uint32_t as = sb + (kc % 3) * STG;
        uint32_t bs = as + 16384;
        #pragma unroll
        for (int kk = 0; kk < 4; kk++) {
            uint32_t a0[4], a1[4];
            ldsm4(a0, sw_addr(as, wm * 32 + (g & 1) * 8 + lr,      kk * 2 + (g >> 1)));
            ldsm4(a1, sw_addr(as, wm * 32 + 16 + (g & 1) * 8 + lr, kk * 2 + (g >> 1)));
            #pragma unroll
            for (int p = 0; p < 4; p++) {
                uint32_t b[4];
                ldsm4(b, sw_addr(bs, wn * 64 + p * 16 + (g & 1) * 8 + lr, kk * 2 + (g >> 1)));
                mma16816(acc[0][2*p],   a0, b[0], b[2]);
                mma16816(acc[0][2*p+1], a0, b[1], b[3]);
                mma16816(acc[1][2*p],   a1, b[0], b[2]);
                mma16816(acc[1][2*p+1], a1, b[1], b[3]);
            }
        }
        if (kc + 2 < nk)
            issue_stage(A, Bm, K, tileM, tileN, sb + ((kc + 2) % 3) * STG, (kc + 2) * 64);
        CP_COMMIT;
    }
    __syncthreads();
}

#define GEMM_EPI_COORDS                                             \
    const int lane = threadIdx.x & 31, warp = threadIdx.x >> 5;     \
    const int wm = warp & 3, wn = warp >> 2;                        \
    const int qd = lane >> 2, c2 = (lane & 3) << 1;                 \
    const int tileM = blockIdx.y * 128, tileN = blockIdx.x * 128;

// qkv: split cols (k,q,v), scale q by 1/8, scatter to [b,h,s,d]; packed 4B stores
__global__ void __launch_bounds__(256) k_qkv() {
    extern __shared__ char dsm[];
    float acc[2][8][4];
    gemm_core(g_xmod, g_wqT, Hc, blockIdx.y * 128, blockIdx.x * 128, dsm, acc);
    GEMM_EPI_COORDS
    #pragma unroll
    for (int mf = 0; mf < 2; mf++)
        #pragma unroll
        for (int nf = 0; nf < 8; nf++)
            #pragma unroll
            for (int half = 0; half < 2; half++) {   // half=0 -> i 0,1 ; half=1 -> i 2,3
                int r  = tileM + wm * 32 + mf * 16 + qd + half * 8;
                int cc = tileN + wn * 64 + nf * 8 + c2;
                int t = cc >> 10, rem = cc & 1023;
                int hh = rem >> 6, d = rem & 63;
                int b = r >> 10, s = r & 1023;
                float sc = (t == 1) ? 0.125f : 1.f;
                uint32_t pk = pack_bf162(acc[mf][nf][half*2] * sc,
                                         acc[mf][nf][half*2+1] * sc);
                bf16* dst = ((t == 0) ? g_k : (t == 1) ? g_q : g_v)
                            + (((size_t)(b * NHc + hh)) * Sc + s) * DHc + d;
                *(uint32_t*)dst = pk;
            }
}

// attn-out: x_res = x + gate_msa*acc ; sumsq_attn (vectorized f32x2)
__global__ void __launch_bounds__(256) k_attnout(const float* __restrict__ x_in) {
    extern __shared__ char dsm[];
    float* sm8 = (float*)(dsm + 98304);
    float acc[2][8][4];
    gemm_core(g_y, g_woT, Hc, blockIdx.y * 128, blockIdx.x * 128, dsm, acc);
    GEMM_EPI_COORDS
    float ss = 0.f;
    #pragma unroll
    for (int mf = 0; mf < 2; mf++)
        #pragma unroll
        for (int nf = 0; nf < 8; nf++)
            #pragma unroll
            for (int half = 0; half < 2; half++) {
                int r  = tileM + wm * 32 + mf * 16 + qd + half * 8;
                int cc = tileN + wn * 64 + nf * 8 + c2;
                int b = r >> 10;
                size_t idx = (size_t)r * Hc + cc;
                float2 g2 = *(const float2*)&g_cm[b * 6 * Hc + 2 * Hc + cc];
                float2 xv = *(const float2*)&x_in[idx];
                float a0 = g2.x * acc[mf][nf][half*2];
                float a1 = g2.y * acc[mf][nf][half*2+1];
                float2 o2 = make_float2(xv.x + a0, xv.y + a1);
                *(float2*)&g_xres[idx] = o2;
                ss += a0 * a0 + a1 * a1;
            }
    float t = block_sum256(ss, sm8);
    if (threadIdx.x == 0) atomicAdd(&g_acc[2], t);
}

// mlp1: positive counts, sumsq_relu, tanh-gelu -> bf16 h (packed 4B stores)
__global__ void __launch_bounds__(256) k_mlp1() {
    extern __shared__ char dsm[];
    float* sm8 = (float*)(dsm + 98304);
    int* scnt = (int*)(dsm + 98368);
    if (threadIdx.x < 128) scnt[threadIdx.x] = 0;
    float acc[2][8][4];
    gemm_core(g_xmod, g_w1T, Hc, blockIdx.y * 128, blockIdx.x * 128, dsm, acc);
    GEMM_EPI_COORDS
    float ss = 0.f;
    #pragma unroll
    for (int nf = 0; nf < 8; nf++) {
        int cnt0 = 0, cnt1 = 0;
        #pragma unroll
        for (int mf = 0; mf < 2; mf++)
            #pragma unroll
            for (int half = 0; half < 2; half++) {
                float t0 = acc[mf][nf][half*2], t1 = acc[mf][nf][half*2+1];
                ss += t0 * t0 + t1 * t1;
                cnt0 += (t0 > 0.f); cnt1 += (t1 > 0.f);
                float u0 = 0.7978845608028654f * (t0 + 0.044715f * t0 * t0 * t0);
                float u1 = 0.7978845608028654f * (t1 + 0.044715f * t1 * t1 * t1);
                float g0 = 0.5f * t0 * (1.f + tanhf(u0));
                float g1 = 0.5f * t1 * (1.f + tanhf(u1));
                int r  = tileM + wm * 32 + mf * 16 + qd + half * 8;
                int cc = tileN + wn * 64 + nf * 8 + c2;
                *(uint32_t*)&g_h[(size_t)r * MLPc + cc] = pack_bf162(g0, g1);
            }
        atomicAdd(&scnt[wn * 64 + nf * 8 + c2], cnt0);
        atomicAdd(&scnt[wn * 64 + nf * 8 + c2 + 1], cnt1);
    }
    __syncthreads();
    if (threadIdx.x < 128) atomicAdd(&g_pos[tileN + threadIdx.x], scnt[threadIdx.x]);
    float t = block_sum256(ss, sm8);
    if (threadIdx.x == 0) atomicAdd(&g_acc[4], t);
}

// mlp2: out = x_res + gate_mlp*acc ; sumsq_mlp (vectorized f32x2)
__global__ void __launch_bounds__(256) k_mlp2(float* __restrict__ out) {
    extern __shared__ char dsm[];
    float* sm8 = (float*)(dsm + 98304);
    float acc[2][8][4];
    gemm_core(g_h, g_w2T, MLPc, blockIdx.y * 128, blockIdx.x * 128, dsm, acc);
    GEMM_EPI_COORDS
    float ss = 0.f;
    #pragma unroll
    for (int mf = 0; mf < 2; mf++)
        #pragma unroll
        for (int nf = 0; nf < 8; nf++)
            #pragma unroll
            for (int half = 0; half < 2; half++) {
                int r  = tileM + wm * 32 + mf * 16 + qd + half * 8;
                int cc = tileN + wn * 64 + nf * 8 + c2;
                int b = r >> 10;
                size_t idx = (size_t)r * Hc + cc;
                float2 g2 = *(const float2*)&g_cm[b * 6 * Hc + 5 * Hc + cc];
                float2 xr = *(const float2*)&g_xres[idx];
                float m0 = g2.x * acc[mf][nf][half*2];
                float m1 = g2.y * acc[mf][nf][half*2+1];
                *(float2*)&out[idx] = make_float2(xr.x + m0, xr.y + m1);
                ss += m0 * m0 + m1 * m1;
            }
    float t = block_sum256(ss, sm8);
    if (threadIdx.x == 0) atomicAdd(&g_acc[5], t);
}

// ---------------- flash attention: cp.async double-buffered + ldmatrix ----------------
// smem: Q @0 (16KB), K @16384 (+buf*8192), V @32768 (+buf*8192), sm8 @49152
#define ATT_SMEM 49216
__global__ void __launch_bounds__(256) k_attn() {
    extern __shared__ char dsm[];
    uint32_t sb = smem_u32(dsm);
    uint32_t Qs = sb, Ks = sb + 16384, Vs = sb + 32768;
    float* sm8 = (float*)(dsm + 49152);
    const int tid = threadIdx.x, lane = tid & 31, w = tid >> 5;
    const int g = lane >> 3, lr = lane & 7;
    const int bh = blockIdx.y, qt = blockIdx.x;

    const bf16* Qg = g_q + ((size_t)bh * Sc + qt * 128) * DHc;
    const bf16* Kg = g_k + (size_t)bh * Sc * DHc;
    const bf16* Vg = g_v + (size_t)bh * Sc * DHc;

    // group 0: Q + K/V tile 0
    #pragma unroll
    for (int t = 0; t < 4; t++) {
        int ch = tid + t * 256;
        int row = ch >> 3, c = ch & 7;
        cp_async16(sw_addr(Qs, row, c), Qg + (size_t)row * DHc + c * 8);
    }
    #pragma unroll
    for (int t = 0; t < 2; t++) {
        int ch = tid + t * 256;
        int row = ch >> 3, c = ch & 7;
        cp_async16(sw_addr(Ks, row, c), Kg + (size_t)row * DHc + c * 8);
        cp_async16(sw_addr(Vs, row, c), Vg + (size_t)row * DHc + c * 8);
    }
    CP_COMMIT;

    uint32_t qa[4][4];
    float O[8][4];
    #pragma unroll
    for (int nf = 0; nf < 8; nf++)
        #pragma unroll
        for (int i = 0; i < 4; i++) O[nf][i] = 0.f;
    float m0 = -1e30f, m1 = -1e30f, l0 = 0.f, l1 = 0.f;

    for (int kt = 0; kt < Sc / 64; kt++) {
        if (kt + 1 < Sc / 64) {
            int buf = (kt + 1) & 1;
            const bf16* Kn = Kg + (size_t)(kt + 1) * 64 * DHc;
            const bf16* Vn = Vg + (size_t)(kt + 1) * 64 * DHc;
            #pragma unroll
            for (int t = 0; t < 2; t++) {
                int ch = tid + t * 256;
                int row = ch >> 3, c = ch & 7;
                cp_async16(sw_addr(Ks + buf * 8192, row, c), Kn + (size_t)row * DHc + c * 8);
                cp_async16(sw_addr(Vs + buf * 8192, row, c), Vn + (size_t)row * DHc + c * 8);
            }
            CP_COMMIT;
            CP_WAIT1;
        } else {
            CP_WAIT0;
        }
        __syncthreads();
        if (kt == 0) {
            #pragma unroll
            for (int kk = 0; kk < 4; kk++)
                ldsm4(qa[kk], sw_addr(Qs, w * 16 + (g & 1) * 8 + lr, kk * 2 + (g >> 1)));
        }
        uint32_t kb = Ks + (kt & 1) * 8192;
        uint32_t vb = Vs + (kt & 1) * 8192;

        float L[8][4];
        #pragma unroll
        for (int nf = 0; nf < 8; nf++)
            #pragma unroll
            for (int i = 0; i < 4; i++) L[nf][i] = 0.f;
        #pragma unroll
        for (int kk = 0; kk < 4; kk++) {
            #pragma unroll
            for (int p = 0; p < 4; p++) {
                uint32_t b[4];
                ldsm4(b, sw_addr(kb, p * 16 + (g & 1) * 8 + lr, kk * 2 + (g >> 1)));
                mma16816(L[2*p],   qa[kk], b[0], b[2]);
                mma16816(L[2*p+1], qa[kk], b[1], b[3]);
            }
        }
        // online softmax (rows qd and qd+8; stats shared across quad)
        float tm0 = -1e30f, tm1 = -1e30f;
        #pragma unroll
        for (int nf = 0; nf < 8; nf++) {
            tm0 = fmaxf(tm0, fmaxf(L[nf][0], L[nf][1]));
            tm1 = fmaxf(tm1, fmaxf(L[nf][2], L[nf][3]));
        }
        tm0 = fmaxf(tm0, __shfl_xor_sync(0xffffffffu, tm0, 1));
        tm0 = fmaxf(tm0, __shfl_xor_sync(0xffffffffu, tm0, 2));
        tm1 = fmaxf(tm1, __shfl_xor_sync(0xffffffffu, tm1, 1));
        tm1 = fmaxf(tm1, __shfl_xor_sync(0xffffffffu, tm1, 2));
        float mn0 = fmaxf(m0, tm0), mn1 = fmaxf(m1, tm1);
        float cor0 = __expf(m0 - mn0), cor1 = __expf(m1 - mn1);
        float s0 = 0.f, s1 = 0.f;
        #pragma unroll
        for (int nf = 0; nf < 8; nf++) {
            L[nf][0] = __expf(L[nf][0] - mn0);
            L[nf][1] = __expf(L[nf][1] - mn0);
            L[nf][2] = __expf(L[nf][2] - mn1);
            L[nf][3] = __expf(L[nf][3] - mn1);
            s0 += L[nf][0] + L[nf][1];
            s1 += L[nf][2] + L[nf][3];
        }
        s0 += __shfl_xor_sync(0xffffffffu, s0, 1);
        s0 += __shfl_xor_sync(0xffffffffu, s0, 2);
        s1 += __shfl_xor_sync(0xffffffffu, s1, 1);
        s1 += __shfl_xor_sync(0xffffffffu, s1, 2);
        l0 = l0 * cor0 + s0; l1 = l1 * cor1 + s1;
        m0 = mn0; m1 = mn1;
        #pragma unroll
        for (int nf = 0; nf < 8; nf++) {
            O[nf][0] *= cor0; O[nf][1] *= cor0;
            O[nf][2] *= cor1; O[nf][3] *= cor1;
        }
        uint32_t pa[4][4];
        #pragma unroll
        for (int kk = 0; kk < 4; kk++) {
            pa[kk][0] = pack_bf162(L[2*kk][0],   L[2*kk][1]);
            pa[kk][1] = pack_bf162(L[2*kk][2],   L[2*kk][3]);
            pa[kk][2] = pack_bf162(L[2*kk+1][0], L[2*kk+1][1]);
            pa[kk][3] = pack_bf162(L[2*kk+1][2], L[2*kk+1][3]);
        }
        #pragma unroll
        for (int kk = 0; kk < 4; kk++) {
            #pragma unroll
            for (int p = 0; p < 4; p++) {
                uint32_t b[4];
                ldsm4t(b, sw_addr(vb, kk * 16 + (g & 1) * 8 + lr, p * 2 + (g >> 1)));
                mma16816(O[2*p],   pa[kk], b[0], b[1]);
                mma16816(O[2*p+1], pa[kk], b[2], b[3]);
            }
        }
        __syncthreads();
    }
    const int qd = lane >> 2, c2 = (lane & 3) << 1;
    float i0 = 1.f / l0, i1 = 1.f / l1;
    int b = bh >> 4, hh = bh & 15;
    int r0 = qt * 128 + w * 16 + qd;
    #pragma unroll
    for (int nf = 0; nf < 8; nf++) {
        size_t base0 = ((size_t)b * Sc + r0)     * Hc + hh * 64 + nf * 8 + c2;
        size_t base1 = ((size_t)b * Sc + r0 + 8) * Hc + hh * 64 + nf * 8 + c2;
        *(uint32_t*)&g_y[base0] = pack_bf162(O[nf][0] * i0, O[nf][1] * i0);
        *(uint32_t*)&g_y[base1] = pack_bf162(O[nf][2] * i1, O[nf][3] * i1);
    }
    float contrib = ((lane & 3) == 0) ? (i0 + i1) : 0.f;
    float t = block_sum256(contrib, sm8);
    if (tid == 0) atomicAdd(&g_acc[1], t);
}

// ---------------- finalize scalars ----------------
__global__ void k_fin(float* __restrict__ out, int out_size) {
    __shared__ float sm8[8];
    int tid = threadIdx.x;
    float dsum = 0.f; int zc = 0, pc = 0;
    for (int j = tid; j < MLPc; j += 256) {
        int c = g_pos[j];
        float fp = c * (1.f / 8192.f);
        dsum += fabsf(fp - 0.5f);
        zc += (c == 0);
        pc += (c == 8192);
    }
    float d = block_sum256(dsum, sm8);
    float z = block_sum256((float)zc, sm8);
    float p = block_sum256((float)pc, sm8);
    if (tid == 0 && out_size != MROWS * Hc) {
        float* o = out + (out_size - 7);
        o[0] = d * (1.f / 4096.f);
        o[1] = z * (1.f / 4096.f);
        o[2] = p * (1.f / 4096.f);
        o[3] = g_acc[1] * (1.f / 131072.f);
        o[4] = sqrtf(g_acc[2] / g_acc[0]);
        o[5] = sqrtf(g_acc[5] / g_acc[3]);
        o[6] = sqrtf(g_acc[4] / (8192.f * 4096.f));
    }
}

// ---------------- launch ----------------
extern "C" void kernel_launch(void* const* d_in, const int* in_sizes, int n_in,
                              void* d_out, int out_size) {
    const float* x      = (const float*)d_in[0];
    const float* c      = (const float*)d_in[1];
    const float* w_cond = (const float*)d_in[2];
    const float* w_qkv  = (const float*)d_in[3];
    const float* w_attn = (const float*)d_in[4];
    const float* w_mlp1 = (const float*)d_in[5];
    const float* w_mlp2 = (const float*)d_in[6];
    float* out = (float*)d_out;

    cudaFuncSetAttribute(k_qkv,     cudaFuncAttributeMaxDynamicSharedMemorySize, SMEM_G);
    cudaFuncSetAttribute(k_attnout, cudaFuncAttributeMaxDynamicSharedMemorySize, SMEM_G);
    cudaFuncSetAttribute(k_mlp1,    cudaFuncAttributeMaxDynamicSharedMemorySize, SMEM_G);
    cudaFuncSetAttribute(k_mlp2,    cudaFuncAttributeMaxDynamicSharedMemorySize, SMEM_G);
    cudaFuncSetAttribute(k_attn,    cudaFuncAttributeMaxDynamicSharedMemorySize, ATT_SMEM);

    k_zero<<<16, 256>>>();
    k_trans<<<dim3(96, 32),  256>>>(w_qkv,  0, Hc,   3*Hc);
    k_trans<<<dim3(32, 32),  256>>>(w_attn, 1, Hc,   Hc);
    k_trans<<<dim3(128, 32), 256>>>(w_mlp1, 2, Hc,   MLPc);
    k_trans<<<dim3(32, 128), 256>>>(w_mlp2, 3, MLPc, Hc);
    k_cond<<<24, 256>>>(c, w_cond);
    k_ln1<<<MROWS, 256>>>(x);
    k_qkv<<<dim3(24, 64), 256, SMEM_G>>>();
    k_attn<<<dim3(8, Bc * NHc), 256, ATT_SMEM>>>();
    k_attnout<<<dim3(8, 64), 256, SMEM_G>>>(x);
    k_ln2<<<MROWS, 256>>>();
    k_mlp1<<<dim3(32, 64), 256, SMEM_G>>>();
    k_mlp2<<<dim3(8, 64), 256, SMEM_G>>>(out);
    k_fin<<<1, 256>>>(out, out_size);
}

// round 9
// speedup vs baseline: 3.7000x; 1.2449x over previous
#include <cuda_runtime.h>
#include <cuda_bf16.h>
#include <stdint.h>
#include <math.h>

typedef __nv_bfloat16 bf16;

#define Bc   8
#define Sc   1024
#define Hc   1024
#define NHc  16
#define DHc  64
#define MLPc 4096
#define MROWS (Bc*Sc)   // 8192

// ---------------- device scratch ----------------
__device__ bf16  g_wqT[3*Hc*Hc];         // [3072,1024] (N,K)
__device__ bf16  g_woT[Hc*Hc];           // [1024,1024]
__device__ bf16  g_w1T[(size_t)MLPc*Hc]; // [4096,1024]
__device__ bf16  g_w2T[(size_t)Hc*MLPc]; // [1024,4096]
__device__ float g_cm[Bc*6*Hc];
__device__ bf16  g_xmod[MROWS*Hc];
__device__ bf16  g_q[Bc*NHc*Sc*DHc];
__device__ bf16  g_k[Bc*NHc*Sc*DHc];
__device__ bf16  g_v[Bc*NHc*Sc*DHc];
__device__ bf16  g_y[MROWS*Hc];
__device__ float g_xres[MROWS*Hc];
__device__ bf16  g_h[(size_t)MROWS*MLPc];
__device__ float g_acc[8];
__device__ int   g_pos[MLPc];

// ---------------- low-level helpers ----------------
__device__ __forceinline__ uint32_t smem_u32(const void* p) {
    uint32_t a;
    asm("{ .reg .u64 t; cvta.to.shared.u64 t, %1; cvt.u32.u64 %0, t; }" : "=r"(a) : "l"(p));
    return a;
}
__device__ __forceinline__ void cp_async16(uint32_t s, const void* g) {
    asm volatile("cp.async.cg.shared.global [%0], [%1], 16;" :: "r"(s), "l"(g));
}
#define CP_COMMIT asm volatile("cp.async.commit_group;" ::: "memory")
#define CP_WAIT1  asm volatile("cp.async.wait_group 1;" ::: "memory")
#define CP_WAIT0  asm volatile("cp.async.wait_group 0;" ::: "memory")

__device__ __forceinline__ uint32_t sw_addr(uint32_t base, int row, int chunk) {
    return base + row * 128 + (((chunk) ^ (row & 7)) << 4);
}
__device__ __forceinline__ void ldsm4(uint32_t r[4], uint32_t a) {
    asm volatile("ldmatrix.sync.aligned.m8n8.x4.shared.b16 {%0,%1,%2,%3}, [%4];"
                 : "=r"(r[0]), "=r"(r[1]), "=r"(r[2]), "=r"(r[3]) : "r"(a));
}
__device__ __forceinline__ void ldsm4t(uint32_t r[4], uint32_t a) {
    asm volatile("ldmatrix.sync.aligned.m8n8.x4.trans.shared.b16 {%0,%1,%2,%3}, [%4];"
                 : "=r"(r[0]), "=r"(r[1]), "=r"(r[2]), "=r"(r[3]) : "r"(a));
}
__device__ __forceinline__ void mma16816(float c[4], const uint32_t a[4],
                                         uint32_t b0, uint32_t b1) {
    asm volatile(
        "mma.sync.aligned.m16n8k16.row.col.f32.bf16.bf16.f32 "
        "{%0,%1,%2,%3},{%4,%5,%6,%7},{%8,%9},{%0,%1,%2,%3};\n"
        : "+f"(c[0]), "+f"(c[1]), "+f"(c[2]), "+f"(c[3])
        : "r"(a[0]), "r"(a[1]), "r"(a[2]), "r"(a[3]), "r"(b0), "r"(b1));
}
__device__ __forceinline__ uint32_t pack_bf162(float x, float y) {
    __nv_bfloat162 h = __floats2bfloat162_rn(x, y);
    return *(uint32_t*)&h;
}
__device__ __forceinline__ float block_sum256(float v, float* sm8) {
    #pragma unroll
    for (int o = 16; o > 0; o >>= 1) v += __shfl_xor_sync(0xffffffffu, v, o);
    __syncthreads();
    if ((threadIdx.x & 31) == 0) sm8[threadIdx.x >> 5] = v;
    __syncthreads();
    float r = 0.f;
    #pragma unroll
    for (int i = 0; i < 8; i++) r += sm8[i];
    return r;
}

// ---------------- small kernels ----------------
__global__ void k_zero() {
    int i = blockIdx.x * 256 + threadIdx.x;
    if (i < Bc * 6 * Hc) g_cm[i] = 0.f;
    if (i < MLPc) g_pos[i] = 0;
    if (i < 8)    g_acc[i] = 0.f;
}

// tiled transpose+convert: src[R,C] f32 -> dst[C,R] bf16.
// Destination selected in device code (sel): passing a __device__ symbol as a
// host-side kernel arg passes the host shadow address (ATS swallows the write).
__global__ void k_trans(const float* __restrict__ src, int sel, int R, int C) {
    bf16* dst = (sel == 0) ? g_wqT : (sel == 1) ? g_woT : (sel == 2) ? g_w1T : g_w2T;
    __shared__ float t[32][33];
    int cb = blockIdx.x * 32, rb = blockIdx.y * 32;
    int tx = threadIdx.x & 31, ty = threadIdx.x >> 5;
    #pragma unroll
    for (int i = 0; i < 32; i += 8)
        t[ty + i][tx] = src[(size_t)(rb + ty + i) * C + cb + tx];
    __syncthreads();
    #pragma unroll
    for (int i = 0; i < 32; i += 8)
        dst[(size_t)(cb + ty + i) * R + rb + tx] = __float2bfloat16(t[tx][ty + i]);
}

// split-K conditioning GEMM: g_cm[b][j] += sum_{k in block} silu(c[b][k]) w[k][j]
__global__ void k_cond(const float* __restrict__ c, const float* __restrict__ w) {
    __shared__ float ssil[Bc * 128];
    int tid = threadIdx.x;
    int kb = blockIdx.y * 128;
    for (int i = tid; i < Bc * 128; i += 256) {
        int b = i >> 7, k = i & 127;
        float v = c[b * Hc + kb + k];
        ssil[i] = v / (1.f + expf(-v));
    }
    __syncthreads();
    int j = blockIdx.x * 256 + tid;
    float acc[Bc];
    #pragma unroll
    for (int b = 0; b < Bc; b++) acc[b] = 0.f;
    for (int k = 0; k < 128; k++) {
        float wv = w[(size_t)(kb + k) * (6 * Hc) + j];
        #pragma unroll
        for (int b = 0; b < Bc; b++) acc[b] += ssil[b * 128 + k] * wv;
    }
    #pragma unroll
    for (int b = 0; b < Bc; b++) atomicAdd(&g_cm[b * 6 * Hc + j], acc[b]);
}

// LayerNorm (fp32 stats, bf16 output) + adaLN modulate -> bf16
__device__ __forceinline__ void ln_impl(const float* __restrict__ xin,
                                        bf16* __restrict__ xout,
                                        int so, int sco, float* ssq) {
    __shared__ float sm8[8];
    int row = blockIdx.x;
    int b = row >> 10;
    int tid = threadIdx.x;
    const float* xr = xin + (size_t)row * Hc;
    float v[4];
    #pragma unroll
    for (int i = 0; i < 4; i++) v[i] = xr[tid + i * 256];
    float s = v[0] + v[1] + v[2] + v[3];
    float mean = block_sum256(s, sm8) * (1.f / 1024.f);
    float s2 = 0.f;
    #pragma unroll
    for (int i = 0; i < 4; i++) { float d = v[i] - mean; s2 += d * d; }
    float var = block_sum256(s2, sm8) * (1.f / 1024.f);
    float rstd = rsqrtf(var + 1e-6f);
    const float* cmb = g_cm + b * 6 * Hc;
    #pragma unroll
    for (int i = 0; i < 4; i++) {
        int col = tid + i * 256;
        float lnv = __bfloat162float(__float2bfloat16((v[i] - mean) * rstd));
        float xm = lnv * cmb[sco * Hc + col] + cmb[so * Hc + col];
        xout[(size_t)row * Hc + col] = __float2bfloat16(xm);
    }
    if (ssq) {
        float q = v[0]*v[0] + v[1]*v[1] + v[2]*v[2] + v[3]*v[3];
        float t = block_sum256(q, sm8);
        if (tid == 0) atomicAdd(ssq, t);
    }
}
__global__ void k_ln1(const float* __restrict__ x) { ln_impl(x, g_xmod, 0, 1, &g_acc[0]); }
__global__ void k_ln2()                             { ln_impl(g_xres, g_xmod, 3, 4, &g_acc[3]); }

// ---------------- pipelined mma.sync GEMM core (validated R7/R8) ----------------
// BM=128, BN=128, BK=64, 3 cp.async stages, 256 threads (8 warps: 4m x 2n).
#define STG 32768
#define SMEM_G 100352

__device__ __forceinline__ void issue_stage(const bf16* __restrict__ A,
                                            const bf16* __restrict__ Bm, int K,
                                            int tileM, int tileN, uint32_t sbase, int kt) {
    const int tid = threadIdx.x;
    #pragma unroll
    for (int t = 0; t < 4; t++) {
        int ch = tid + t * 256;
        int row = ch >> 3, c = ch & 7;
        cp_async16(sw_addr(sbase, row, c), A + (size_t)(tileM + row) * K + kt + c * 8);
    }
    #pragma unroll
    for (int t = 0; t < 4; t++) {
        int ch = tid + t * 256;
        int row = ch >> 3, c = ch & 7;
        cp_async16(sw_addr(sbase + 16384, row, c), Bm + (size_t)(tileN + row) * K + kt + c * 8);
    }
}

__device__ __forceinline__ void gemm_core(const bf16* __restrict__ A,
                                          const bf16* __restrict__ Bm, int K,
                                          int tileM, int tileN, char* dsm,
                                          float acc[2][8][4]) {
    uint32_t sb = smem_u32(dsm);
    const int tid = threadIdx.x, lane = tid & 31, warp = tid >> 5;
    const int wm = warp & 3, wn = warp >> 2;
    const int g = lane >> 3, lr = lane & 7;
    #pragma unroll
    for (int mf = 0; mf < 2; mf++)
        #pragma unroll
        for (int nf = 0; nf < 8; nf++)
            #pragma unroll
            for (int i = 0; i < 4; i++) acc[mf][nf][i] = 0.f;

    const int nk = K >> 6;
    issue_stage(A, Bm, K, tileM, tileN, sb, 0);          CP_COMMIT;
    issue_stage(A, Bm, K, tileM, tileN, sb + STG, 64);   CP_COMMIT;

    for (int kc = 0; kc < nk; kc++) {
        CP_WAIT1;
        __syncthreads();
        uint32_t as = sb + (kc % 3) * STG;
        uint32_t bs = as + 16384;
        #pragma unroll
        for (int kk = 0; kk < 4; kk++) {
            uint32_t a0[4], a1[4];
            ldsm4(a0, sw_addr(as, wm * 32 + (g & 1) * 8 + lr,      kk * 2 + (g >> 1)));
            ldsm4(a1, sw_addr(as, wm * 32 + 16 + (g & 1) * 8 + lr, kk * 2 + (g >> 1)));
            #pragma unroll
            for (int p = 0; p < 4; p++) {
                uint32_t b[4];
                ldsm4(b, sw_addr(bs, wn * 64 + p * 16 + (g & 1) * 8 + lr, kk * 2 + (g >> 1)));
                mma16816(acc[0][2*p],   a0, b[0], b[2]);
                mma16816(acc[0][2*p+1], a0, b[1], b[3]);
                mma16816(acc[1][2*p],   a1, b[0], b[2]);
                mma16816(acc[1][2*p+1], a1, b[1], b[3]);
            }
        }
        if (kc + 2 < nk)
            issue_stage(A, Bm, K, tileM, tileN, sb + ((kc + 2) % 3) * STG, (kc + 2) * 64);
        CP_COMMIT;
    }
    __syncthreads();
}

#define GEMM_EPI_COORDS                                             \
    const int lane = threadIdx.x & 31, warp = threadIdx.x >> 5;     \
    const int wm = warp & 3, wn = warp >> 2;                        \
    const int qd = lane >> 2, c2 = (lane & 3) << 1;                 \
    const int tileM = blockIdx.y * 128, tileN = blockIdx.x * 128;

// qkv: split cols (k,q,v), scale q by 1/8, scatter to [b,h,s,d]; packed 4B stores
__global__ void __launch_bounds__(256, 2) k_qkv() {
    extern __shared__ char dsm[];
    float acc[2][8][4];
    gemm_core(g_xmod, g_wqT, Hc, blockIdx.y * 128, blockIdx.x * 128, dsm, acc);
    GEMM_EPI_COORDS
    #pragma unroll
    for (int mf = 0; mf < 2; mf++)
        #pragma unroll
        for (int nf = 0; nf < 8; nf++)
            #pragma unroll
            for (int half = 0; half < 2; half++) {
                int r  = tileM + wm * 32 + mf * 16 + qd + half * 8;
                int cc = tileN + wn * 64 + nf * 8 + c2;
                int t = cc >> 10, rem = cc & 1023;
                int hh = rem >> 6, d = rem & 63;
                int b = r >> 10, s = r & 1023;
                float sc = (t == 1) ? 0.125f : 1.f;
                uint32_t pk = pack_bf162(acc[mf][nf][half*2] * sc,
                                         acc[mf][nf][half*2+1] * sc);
                bf16* dst = ((t == 0) ? g_k : (t == 1) ? g_q : g_v)
                            + (((size_t)(b * NHc + hh)) * Sc + s) * DHc + d;
                *(uint32_t*)dst = pk;
            }
}

// attn-out: x_res = x + gate_msa*acc ; sumsq_attn (vectorized f32x2)
__global__ void __launch_bounds__(256, 2) k_attnout(const float* __restrict__ x_in) {
    extern __shared__ char dsm[];
    float* sm8 = (float*)(dsm + 98304);
    float acc[2][8][4];
    gemm_core(g_y, g_woT, Hc, blockIdx.y * 128, blockIdx.x * 128, dsm, acc);
    GEMM_EPI_COORDS
    float ss = 0.f;
    #pragma unroll
    for (int mf = 0; mf < 2; mf++)
        #pragma unroll
        for (int nf = 0; nf < 8; nf++)
            #pragma unroll
            for (int half = 0; half < 2; half++) {
                int r  = tileM + wm * 32 + mf * 16 + qd + half * 8;
                int cc = tileN + wn * 64 + nf * 8 + c2;
                int b = r >> 10;
                size_t idx = (size_t)r * Hc + cc;
                float2 g2 = *(const float2*)&g_cm[b * 6 * Hc + 2 * Hc + cc];
                float2 xv = *(const float2*)&x_in[idx];
                float a0 = g2.x * acc[mf][nf][half*2];
                float a1 = g2.y * acc[mf][nf][half*2+1];
                *(float2*)&g_xres[idx] = make_float2(xv.x + a0, xv.y + a1);
                ss += a0 * a0 + a1 * a1;
            }
    float t = block_sum256(ss, sm8);
    if (threadIdx.x == 0) atomicAdd(&g_acc[2], t);
}

// mlp1: positive counts, sumsq_relu, tanh-gelu -> bf16 h (packed 4B stores)
__global__ void __launch_bounds__(256, 2) k_mlp1() {
    extern __shared__ char dsm[];
    float* sm8 = (float*)(dsm + 98304);
    int* scnt = (int*)(dsm + 98368);
    if (threadIdx.x < 128) scnt[threadIdx.x] = 0;
    float acc[2][8][4];
    gemm_core(g_xmod, g_w1T, Hc, blockIdx.y * 128, blockIdx.x * 128, dsm, acc);
    GEMM_EPI_COORDS
    float ss = 0.f;
    #pragma unroll
    for (int nf = 0; nf < 8; nf++) {
        int cnt0 = 0, cnt1 = 0;
        #pragma unroll
        for (int mf = 0; mf < 2; mf++)
            #pragma unroll
            for (int half = 0; half < 2; half++) {
                float t0 = acc[mf][nf][half*2], t1 = acc[mf][nf][half*2+1];
                ss += t0 * t0 + t1 * t1;
                cnt0 += (t0 > 0.f); cnt1 += (t1 > 0.f);
                float u0 = 0.7978845608028654f * (t0 + 0.044715f * t0 * t0 * t0);
                float u1 = 0.7978845608028654f * (t1 + 0.044715f * t1 * t1 * t1);
                float g0 = 0.5f * t0 * (1.f + tanhf(u0));
                float g1 = 0.5f * t1 * (1.f + tanhf(u1));
                int r  = tileM + wm * 32 + mf * 16 + qd + half * 8;
                int cc = tileN + wn * 64 + nf * 8 + c2;
                *(uint32_t*)&g_h[(size_t)r * MLPc + cc] = pack_bf162(g0, g1);
            }
        atomicAdd(&scnt[wn * 64 + nf * 8 + c2], cnt0);
        atomicAdd(&scnt[wn * 64 + nf * 8 + c2 + 1], cnt1);
    }
    __syncthreads();
    if (threadIdx.x < 128) atomicAdd(&g_pos[tileN + threadIdx.x], scnt[threadIdx.x]);
    float t = block_sum256(ss, sm8);
    if (threadIdx.x == 0) atomicAdd(&g_acc[4], t);
}

// mlp2: out = x_res + gate_mlp*acc ; sumsq_mlp (vectorized f32x2)
__global__ void __launch_bounds__(256, 2) k_mlp2(float* __restrict__ out) {
    extern __shared__ char dsm[];
    float* sm8 = (float*)(dsm + 98304);
    float acc[2][8][4];
    gemm_core(g_h, g_w2T, MLPc, blockIdx.y * 128, blockIdx.x * 128, dsm, acc);
    GEMM_EPI_COORDS
    float ss = 0.f;
    #pragma unroll
    for (int mf = 0; mf < 2; mf++)
        #pragma unroll
        for (int nf = 0; nf < 8; nf++)
            #pragma unroll
            for (int half = 0; half < 2; half++) {
                int r  = tileM + wm * 32 + mf * 16 + qd + half * 8;
                int cc = tileN + wn * 64 + nf * 8 + c2;
                int b = r >> 10;
                size_t idx = (size_t)r * Hc + cc;
                float2 g2 = *(const float2*)&g_cm[b * 6 * Hc + 5 * Hc + cc];
                float2 xr = *(const float2*)&g_xres[idx];
                float m0 = g2.x * acc[mf][nf][half*2];
                float m1 = g2.y * acc[mf][nf][half*2+1];
                *(float2*)&out[idx] = make_float2(xr.x + m0, xr.y + m1);
                ss += m0 * m0 + m1 * m1;
            }
    float t = block_sum256(ss, sm8);
    if (threadIdx.x == 0) atomicAdd(&g_acc[5], t);
}

// ---------------- flash attention: cp.async double-buffered + ldmatrix ----------------
// smem: Q @0 (16KB), K @16384 (+buf*8192), V @32768 (+buf*8192), sm8 @49152
#define ATT_SMEM 49216
__global__ void __launch_bounds__(256) k_attn() {
    extern __shared__ char dsm[];
    uint32_t sb = smem_u32(dsm);
    uint32_t Qs = sb, Ks = sb + 16384, Vs = sb + 32768;
    float* sm8 = (float*)(dsm + 49152);
    const int tid = threadIdx.x, lane = tid & 31, w = tid >> 5;
    const int g = lane >> 3, lr = lane & 7;
    const int bh = blockIdx.y, qt = blockIdx.x;

    const bf16* Qg = g_q + ((size_t)bh * Sc + qt * 128) * DHc;
    const bf16* Kg = g_k + (size_t)bh * Sc * DHc;
    const bf16* Vg = g_v + (size_t)bh * Sc * DHc;

    #pragma unroll
    for (int t = 0; t < 4; t++) {
        int ch = tid + t * 256;
        int row = ch >> 3, c = ch & 7;
        cp_async16(sw_addr(Qs, row, c), Qg + (size_t)row * DHc + c * 8);
    }
    #pragma unroll
    for (int t = 0; t < 2; t++) {
        int ch = tid + t * 256;
        int row = ch >> 3, c = ch & 7;
        cp_async16(sw_addr(Ks, row, c), Kg + (size_t)row * DHc + c * 8);
        cp_async16(sw_addr(Vs, row, c), Vg + (size_t)row * DHc + c * 8);
    }
    CP_COMMIT;

    uint32_t qa[4][4];
    float O[8][4];
    #pragma unroll
    for (int nf = 0; nf < 8; nf++)
        #pragma unroll
        for (int i = 0; i < 4; i++) O[nf][i] = 0.f;
    float m0 = -1e30f, m1 = -1e30f, l0 = 0.f, l1 = 0.f;

    for (int kt = 0; kt < Sc / 64; kt++) {
        if (kt + 1 < Sc / 64) {
            int buf = (kt + 1) & 1;
            const bf16* Kn = Kg + (size_t)(kt + 1) * 64 * DHc;
            const bf16* Vn = Vg + (size_t)(kt + 1) * 64 * DHc;
            #pragma unroll
            for (int t = 0; t < 2; t++) {
                int ch = tid + t * 256;
                int row = ch >> 3, c = ch & 7;
                cp_async16(sw_addr(Ks + buf * 8192, row, c), Kn + (size_t)row * DHc + c * 8);
                cp_async16(sw_addr(Vs + buf * 8192, row, c), Vn + (size_t)row * DHc + c * 8);
            }
            CP_COMMIT;
            CP_WAIT1;
        } else {
            CP_WAIT0;
        }
        __syncthreads();
        if (kt == 0) {
            #pragma unroll
            for (int kk = 0; kk < 4; kk++)
                ldsm4(qa[kk], sw_addr(Qs, w * 16 + (g & 1) * 8 + lr, kk * 2 + (g >> 1)));
        }
        uint32_t kb = Ks + (kt & 1) * 8192;
        uint32_t vb = Vs + (kt & 1) * 8192;

        float L[8][4];
        #pragma unroll
        for (int nf = 0; nf < 8; nf++)
            #pragma unroll
            for (int i = 0; i < 4; i++) L[nf][i] = 0.f;
        #pragma unroll
        for (int kk = 0; kk < 4; kk++) {
            #pragma unroll
            for (int p = 0; p < 4; p++) {
                uint32_t b[4];
                ldsm4(b, sw_addr(kb, p * 16 + (g & 1) * 8 + lr, kk * 2 + (g >> 1)));
                mma16816(L[2*p],   qa[kk], b[0], b[2]);
                mma16816(L[2*p+1], qa[kk], b[1], b[3]);
            }
        }
        float tm0 = -1e30f, tm1 = -1e30f;
        #pragma unroll
        for (int nf = 0; nf < 8; nf++) {
            tm0 = fmaxf(tm0, fmaxf(L[nf][0], L[nf][1]));
            tm1 = fmaxf(tm1, fmaxf(L[nf][2], L[nf][3]));
        }
        tm0 = fmaxf(tm0, __shfl_xor_sync(0xffffffffu, tm0, 1));
        tm0 = fmaxf(tm0, __shfl_xor_sync(0xffffffffu, tm0, 2));
        tm1 = fmaxf(tm1, __shfl_xor_sync(0xffffffffu, tm1, 1));
        tm1 = fmaxf(tm1, __shfl_xor_sync(0xffffffffu, tm1, 2));
        float mn0 = fmaxf(m0, tm0), mn1 = fmaxf(m1, tm1);
        float cor0 = __expf(m0 - mn0), cor1 = __expf(m1 - mn1);
        float s0 = 0.f, s1 = 0.f;
        #pragma unroll
        for (int nf = 0; nf < 8; nf++) {
            L[nf][0] = __expf(L[nf][0] - mn0);
            L[nf][1] = __expf(L[nf][1] - mn0);
            L[nf][2] = __expf(L[nf][2] - mn1);
            L[nf][3] = __expf(L[nf][3] - mn1);
            s0 += L[nf][0] + L[nf][1];
            s1 += L[nf][2] + L[nf][3];
        }
        s0 += __shfl_xor_sync(0xffffffffu, s0, 1);
        s0 += __shfl_xor_sync(0xffffffffu, s0, 2);
        s1 += __shfl_xor_sync(0xffffffffu, s1, 1);
        s1 += __shfl_xor_sync(0xffffffffu, s1, 2);
        l0 = l0 * cor0 + s0; l1 = l1 * cor1 + s1;
        m0 = mn0; m1 = mn1;
        #pragma unroll
        for (int nf = 0; nf < 8; nf++) {
            O[nf][0] *= cor0; O[nf][1] *= cor0;
            O[nf][2] *= cor1; O[nf][3] *= cor1;
        }
        uint32_t pa[4][4];
        #pragma unroll
        for (int kk = 0; kk < 4; kk++) {
            pa[kk][0] = pack_bf162(L[2*kk][0],   L[2*kk][1]);
            pa[kk][1] = pack_bf162(L[2*kk][2],   L[2*kk][3]);
            pa[kk][2] = pack_bf162(L[2*kk+1][0], L[2*kk+1][1]);
            pa[kk][3] = pack_bf162(L[2*kk+1][2], L[2*kk+1][3]);
        }
        #pragma unroll
        for (int kk = 0; kk < 4; kk++) {
            #pragma unroll
            for (int p = 0; p < 4; p++) {
                uint32_t b[4];
                ldsm4t(b, sw_addr(vb, kk * 16 + (g & 1) * 8 + lr, p * 2 + (g >> 1)));
                mma16816(O[2*p],   pa[kk], b[0], b[1]);
                mma16816(O[2*p+1], pa[kk], b[2], b[3]);
            }
        }
        __syncthreads();
    }
    const int qd = lane >> 2, c2 = (lane & 3) << 1;
    float i0 = 1.f / l0, i1 = 1.f / l1;
    int b = bh >> 4, hh = bh & 15;
    int r0 = qt * 128 + w * 16 + qd;
    #pragma unroll
    for (int nf = 0; nf < 8; nf++) {
        size_t base0 = ((size_t)b * Sc + r0)     * Hc + hh * 64 + nf * 8 + c2;
        size_t base1 = ((size_t)b * Sc + r0 + 8) * Hc + hh * 64 + nf * 8 + c2;
        *(uint32_t*)&g_y[base0] = pack_bf162(O[nf][0] * i0, O[nf][1] * i0);
        *(uint32_t*)&g_y[base1] = pack_bf162(O[nf][2] * i1, O[nf][3] * i1);
    }
    float contrib = ((lane & 3) == 0) ? (i0 + i1) : 0.f;
    float t = block_sum256(contrib, sm8);
    if (tid == 0) atomicAdd(&g_acc[1], t);
}

// ---------------- finalize scalars ----------------
__global__ void k_fin(float* __restrict__ out, int out_size) {
    __shared__ float sm8[8];
    int tid = threadIdx.x;
    float dsum = 0.f; int zc = 0, pc = 0;
    for (int j = tid; j < MLPc; j += 256) {
        int c = g_pos[j];
        float fp = c * (1.f / 8192.f);
        dsum += fabsf(fp - 0.5f);
        zc += (c == 0);
        pc += (c == 8192);
    }
    float d = block_sum256(dsum, sm8);
    float z = block_sum256((float)zc, sm8);
    float p = block_sum256((float)pc, sm8);
    if (tid == 0 && out_size != MROWS * Hc) {
        float* o = out + (out_size - 7);
        o[0] = d * (1.f / 4096.f);
        o[1] = z * (1.f / 4096.f);
        o[2] = p * (1.f / 4096.f);
        o[3] = g_acc[1] * (1.f / 131072.f);
        o[4] = sqrtf(g_acc[2] / g_acc[0]);
        o[5] = sqrtf(g_acc[5] / g_acc[3]);
        o[6] = sqrtf(g_acc[4] / (8192.f * 4096.f));
    }
}

// ---------------- launch ----------------
extern "C" void kernel_launch(void* const* d_in, const int* in_sizes, int n_in,
                              void* d_out, int out_size) {
    const float* x      = (const float*)d_in[0];
    const float* c      = (const float*)d_in[1];
    const float* w_cond = (const float*)d_in[2];
    const float* w_qkv  = (const float*)d_in[3];
    const float* w_attn = (const float*)d_in[4];
    const float* w_mlp1 = (const float*)d_in[5];
    const float* w_mlp2 = (const float*)d_in[6];
    float* out = (float*)d_out;

    cudaFuncSetAttribute(k_qkv,     cudaFuncAttributeMaxDynamicSharedMemorySize, SMEM_G);
    cudaFuncSetAttribute(k_attnout, cudaFuncAttributeMaxDynamicSharedMemorySize, SMEM_G);
    cudaFuncSetAttribute(k_mlp1,    cudaFuncAttributeMaxDynamicSharedMemorySize, SMEM_G);
    cudaFuncSetAttribute(k_mlp2,    cudaFuncAttributeMaxDynamicSharedMemorySize, SMEM_G);
    cudaFuncSetAttribute(k_attn,    cudaFuncAttributeMaxDynamicSharedMemorySize, ATT_SMEM);

    k_zero<<<192, 256>>>();
    k_trans<<<dim3(96, 32),  256>>>(w_qkv,  0, Hc,   3*Hc);
    k_trans<<<dim3(32, 32),  256>>>(w_attn, 1, Hc,   Hc);
    k_trans<<<dim3(128, 32), 256>>>(w_mlp1, 2, Hc,   MLPc);
    k_trans<<<dim3(32, 128), 256>>>(w_mlp2, 3, MLPc, Hc);
    k_cond<<<dim3(24, 8), 256>>>(c, w_cond);
    k_ln1<<<MROWS, 256>>>(x);
    k_qkv<<<dim3(24, 64), 256, SMEM_G>>>();
    k_attn<<<dim3(8, Bc * NHc), 256, ATT_SMEM>>>();
    k_attnout<<<dim3(8, 64), 256, SMEM_G>>>(x);
    k_ln2<<<MROWS, 256>>>();
    k_mlp1<<<dim3(32, 64), 256, SMEM_G>>>();
    k_mlp2<<<dim3(8, 64), 256, SMEM_G>>>(out);
    k_fin<<<1, 256>>>(out, out_size);
}

// round 10
// speedup vs baseline: 3.7315x; 1.0085x over previous
#include <cuda_runtime.h>
#include <cuda_bf16.h>
#include <stdint.h>
#include <math.h>

typedef __nv_bfloat16 bf16;

#define Bc   8
#define Sc   1024
#define Hc   1024
#define NHc  16
#define DHc  64
#define MLPc 4096
#define MROWS (Bc*Sc)   // 8192

// ---------------- device scratch ----------------
__device__ bf16  g_wqT[3*Hc*Hc];         // [3072,1024] (N,K)
__device__ bf16  g_woT[Hc*Hc];           // [1024,1024]
__device__ bf16  g_w1T[(size_t)MLPc*Hc]; // [4096,1024]
__device__ bf16  g_w2T[(size_t)Hc*MLPc]; // [1024,4096]
__device__ float g_cm[Bc*6*Hc];
__device__ bf16  g_xmod[MROWS*Hc];
__device__ bf16  g_q[Bc*NHc*Sc*DHc];
__device__ bf16  g_k[Bc*NHc*Sc*DHc];
__device__ bf16  g_v[Bc*NHc*Sc*DHc];
__device__ bf16  g_y[MROWS*Hc];
__device__ float g_xres[MROWS*Hc];
__device__ bf16  g_h[(size_t)MROWS*MLPc];
__device__ float g_acc[8];
__device__ int   g_pos[MLPc];

// ---------------- low-level helpers ----------------
__device__ __forceinline__ uint32_t smem_u32(const void* p) {
    uint32_t a;
    asm("{ .reg .u64 t; cvta.to.shared.u64 t, %1; cvt.u32.u64 %0, t; }" : "=r"(a) : "l"(p));
    return a;
}
__device__ __forceinline__ void cp_async16(uint32_t s, const void* g) {
    asm volatile("cp.async.cg.shared.global [%0], [%1], 16;" :: "r"(s), "l"(g));
}
#define CP_COMMIT asm volatile("cp.async.commit_group;" ::: "memory")
#define CP_WAIT1  asm volatile("cp.async.wait_group 1;" ::: "memory")
#define CP_WAIT0  asm volatile("cp.async.wait_group 0;" ::: "memory")

__device__ __forceinline__ uint32_t sw_addr(uint32_t base, int row, int chunk) {
    return base + row * 128 + (((chunk) ^ (row & 7)) << 4);
}
__device__ __forceinline__ void ldsm4(uint32_t r[4], uint32_t a) {
    asm volatile("ldmatrix.sync.aligned.m8n8.x4.shared.b16 {%0,%1,%2,%3}, [%4];"
                 : "=r"(r[0]), "=r"(r[1]), "=r"(r[2]), "=r"(r[3]) : "r"(a));
}
__device__ __forceinline__ void ldsm4t(uint32_t r[4], uint32_t a) {
    asm volatile("ldmatrix.sync.aligned.m8n8.x4.trans.shared.b16 {%0,%1,%2,%3}, [%4];"
                 : "=r"(r[0]), "=r"(r[1]), "=r"(r[2]), "=r"(r[3]) : "r"(a));
}
__device__ __forceinline__ void mma16816(float c[4], const uint32_t a[4],
                                         uint32_t b0, uint32_t b1) {
    asm volatile(
        "mma.sync.aligned.m16n8k16.row.col.f32.bf16.bf16.f32 "
        "{%0,%1,%2,%3},{%4,%5,%6,%7},{%8,%9},{%0,%1,%2,%3};\n"
        : "+f"(c[0]), "+f"(c[1]), "+f"(c[2]), "+f"(c[3])
        : "r"(a[0]), "r"(a[1]), "r"(a[2]), "r"(a[3]), "r"(b0), "r"(b1));
}
__device__ __forceinline__ uint32_t pack_bf162(float x, float y) {
    __nv_bfloat162 h = __floats2bfloat162_rn(x, y);
    return *(uint32_t*)&h;
}
__device__ __forceinline__ float warp_sum32(float v) {
    #pragma unroll
    for (int o = 16; o > 0; o >>= 1) v += __shfl_xor_sync(0xffffffffu, v, o);
    return v;
}
__device__ __forceinline__ float block_sum256(float v, float* sm8) {
    #pragma unroll
    for (int o = 16; o > 0; o >>= 1) v += __shfl_xor_sync(0xffffffffu, v, o);
    __syncthreads();
    if ((threadIdx.x & 31) == 0) sm8[threadIdx.x >> 5] = v;
    __syncthreads();
    float r = 0.f;
    #pragma unroll
    for (int i = 0; i < 8; i++) r += sm8[i];
    return r;
}

// ---------------- small kernels ----------------
__global__ void k_zero() {
    int i = blockIdx.x * 256 + threadIdx.x;
    if (i < Bc * 6 * Hc) g_cm[i] = 0.f;
    if (i < MLPc) g_pos[i] = 0;
    if (i < 8)    g_acc[i] = 0.f;
}

// tiled transpose+convert: src[R,C] f32 -> dst[C,R] bf16 (dst picked in device code)
__global__ void k_trans(const float* __restrict__ src, int sel, int R, int C) {
    bf16* dst = (sel == 0) ? g_wqT : (sel == 1) ? g_woT : (sel == 2) ? g_w1T : g_w2T;
    __shared__ float t[32][33];
    int cb = blockIdx.x * 32, rb = blockIdx.y * 32;
    int tx = threadIdx.x & 31, ty = threadIdx.x >> 5;
    #pragma unroll
    for (int i = 0; i < 32; i += 8)
        t[ty + i][tx] = src[(size_t)(rb + ty + i) * C + cb + tx];
    __syncthreads();
    #pragma unroll
    for (int i = 0; i < 32; i += 8)
        dst[(size_t)(cb + ty + i) * R + rb + tx] = __float2bfloat16(t[tx][ty + i]);
}

// split-K conditioning GEMM
__global__ void k_cond(const float* __restrict__ c, const float* __restrict__ w) {
    __shared__ float ssil[Bc * 128];
    int tid = threadIdx.x;
    int kb = blockIdx.y * 128;
    for (int i = tid; i < Bc * 128; i += 256) {
        int b = i >> 7, k = i & 127;
        float v = c[b * Hc + kb + k];
        ssil[i] = v / (1.f + expf(-v));
    }
    __syncthreads();
    int j = blockIdx.x * 256 + tid;
    float acc[Bc];
    #pragma unroll
    for (int b = 0; b < Bc; b++) acc[b] = 0.f;
    for (int k = 0; k < 128; k++) {
        float wv = w[(size_t)(kb + k) * (6 * Hc) + j];
        #pragma unroll
        for (int b = 0; b < Bc; b++) acc[b] += ssil[b * 128 + k] * wv;
    }
    #pragma unroll
    for (int b = 0; b < Bc; b++) atomicAdd(&g_cm[b * 6 * Hc + j], acc[b]);
}

// Warp-per-row LayerNorm + adaLN modulate -> bf16 (no block syncs in stats path).
// use_xres selects g_xres in device code (device-symbol-as-arg is the R3-R6 bug).
__global__ void __launch_bounds__(256) k_ln_w(const float* __restrict__ xp,
                                              int use_xres, int so, int sco, int acc_idx) {
    __shared__ float sm8[8];
    const float* xin = use_xres ? g_xres : xp;
    const int w = threadIdx.x >> 5, lane = threadIdx.x & 31;
    const int row = blockIdx.x * 8 + w;
    const int b = row >> 10;
    const float* xr = xin + (size_t)row * Hc;
    float4 v[8];
    #pragma unroll
    for (int j = 0; j < 8; j++) v[j] = *(const float4*)(xr + j * 128 + lane * 4);
    float s = 0.f, q = 0.f;
    #pragma unroll
    for (int j = 0; j < 8; j++) {
        s += v[j].x + v[j].y + v[j].z + v[j].w;
        q += v[j].x*v[j].x + v[j].y*v[j].y + v[j].z*v[j].z + v[j].w*v[j].w;
    }
    s = warp_sum32(s);
    float mean = s * (1.f / 1024.f);
    float s2 = 0.f;
    #pragma unroll
    for (int j = 0; j < 8; j++) {
        float d0 = v[j].x - mean, d1 = v[j].y - mean;
        float d2 = v[j].z - mean, d3 = v[j].w - mean;
        s2 += d0*d0 + d1*d1 + d2*d2 + d3*d3;
    }
    s2 = warp_sum32(s2);
    float rstd = rsqrtf(s2 * (1.f / 1024.f) + 1e-6f);
    const float* cmb = g_cm + b * 6 * Hc;
    #pragma unroll
    for (int j = 0; j < 8; j++) {
        int col = j * 128 + lane * 4;
        float4 sc = *(const float4*)(cmb + sco * Hc + col);
        float4 sh = *(const float4*)(cmb + so * Hc + col);
        float l0 = __bfloat162float(__float2bfloat16((v[j].x - mean) * rstd));
        float l1 = __bfloat162float(__float2bfloat16((v[j].y - mean) * rstd));
        float l2 = __bfloat162float(__float2bfloat16((v[j].z - mean) * rstd));
        float l3 = __bfloat162float(__float2bfloat16((v[j].w - mean) * rstd));
        uint2 pk;
        pk.x = pack_bf162(l0 * sc.x + sh.x, l1 * sc.y + sh.y);
        pk.y = pack_bf162(l2 * sc.z + sh.z, l3 * sc.w + sh.w);
        *(uint2*)&g_xmod[(size_t)row * Hc + col] = pk;
    }
    q = warp_sum32(q);
    if (lane == 0) sm8[w] = q;
    __syncthreads();
    if (threadIdx.x == 0) {
        float t = 0.f;
        #pragma unroll
        for (int i = 0; i < 8; i++) t += sm8[i];
        atomicAdd(&g_acc[acc_idx], t);
    }
}

// ---------------- pipelined mma.sync GEMM core (validated R7-R9) ----------------
// BM=128, BN=128, BK=64, 3 cp.async stages, 256 threads (8 warps: 4m x 2n).
#define STG 32768
#define SMEM_G 100352

__device__ __forceinline__ void issue_stage(const bf16* __restrict__ A,
                                            const bf16* __restrict__ Bm, int K,
                                            int tileM, int tileN, uint32_t sbase, int kt) {
    const int tid = threadIdx.x;
    #pragma unroll
    for (int t = 0; t < 4; t++) {
        int ch = tid + t * 256;
        int row = ch >> 3, c = ch & 7;
        cp_async16(sw_addr(sbase, row, c), A + (size_t)(tileM + row) * K + kt + c * 8);
    }
    #pragma unroll
    for (int t = 0; t < 4; t++) {
        int ch = tid + t * 256;
        int row = ch >> 3, c = ch & 7;
        cp_async16(sw_addr(sbase + 16384, row, c), Bm + (size_t)(tileN + row) * K + kt + c * 8);
    }
}

__device__ __forceinline__ void gemm_core(const bf16* __restrict__ A,
                                          const bf16* __restrict__ Bm, int K,
                                          int tileM, int tileN, char* dsm,
                                          float acc[2][8][4]) {
    uint32_t sb = smem_u32(dsm);
    const int tid = threadIdx.x, lane = tid & 31, warp = tid >> 5;
    const int wm = warp & 3, wn = warp >> 2;
    const int g = lane >> 3, lr = lane & 7;
    #pragma unroll
    for (int mf = 0; mf < 2; mf++)
        #pragma unroll
        for (int nf = 0; nf < 8; nf++)
            #pragma unroll
            for (int i = 0; i < 4; i++) acc[mf][nf][i] = 0.f;

    const int nk = K >> 6;
    issue_stage(A, Bm, K, tileM, tileN, sb, 0);          CP_COMMIT;
    issue_stage(A, Bm, K, tileM, tileN, sb + STG, 64);   CP_COMMIT;

    for (int kc = 0; kc < nk; kc++) {
        CP_WAIT1;
        __syncthreads();
        uint32_t as = sb + (kc % 3) * STG;
        uint32_t bs = as + 16384;
        #pragma unroll
        for (int kk = 0; kk < 4; kk++) {
            uint32_t a0[4], a1[4];
            ldsm4(a0, sw_addr(as, wm * 32 + (g & 1) * 8 + lr,      kk * 2 + (g >> 1)));
            ldsm4(a1, sw_addr(as, wm * 32 + 16 + (g & 1) * 8 + lr, kk * 2 + (g >> 1)));
            #pragma unroll
            for (int p = 0; p < 4; p++) {
                uint32_t b[4];
                ldsm4(b, sw_addr(bs, wn * 64 + p * 16 + (g & 1) * 8 + lr, kk * 2 + (g >> 1)));
                mma16816(acc[0][2*p],   a0, b[0], b[2]);
                mma16816(acc[0][2*p+1], a0, b[1], b[3]);
                mma16816(acc[1][2*p],   a1, b[0], b[2]);
                mma16816(acc[1][2*p+1], a1, b[1], b[3]);
            }
        }
        if (kc + 2 < nk)
            issue_stage(A, Bm, K, tileM, tileN, sb + ((kc + 2) % 3) * STG, (kc + 2) * 64);
        CP_COMMIT;
    }
    __syncthreads();
}

#define GEMM_EPI_COORDS                                             \
    const int lane = threadIdx.x & 31, warp = threadIdx.x >> 5;     \
    const int wm = warp & 3, wn = warp >> 2;                        \
    const int qd = lane >> 2, c2 = (lane & 3) << 1;                 \
    const int tileM = blockIdx.y * 128, tileN = blockIdx.x * 128;

// qkv: split cols (k,q,v), scale q by 1/8, scatter to [b,h,s,d]; packed 4B stores
__global__ void __launch_bounds__(256, 2) k_qkv() {
    extern __shared__ char dsm[];
    float acc[2][8][4];
    gemm_core(g_xmod, g_wqT, Hc, blockIdx.y * 128, blockIdx.x * 128, dsm, acc);
    GEMM_EPI_COORDS
    #pragma unroll
    for (int mf = 0; mf < 2; mf++)
        #pragma unroll
        for (int nf = 0; nf < 8; nf++)
            #pragma unroll
            for (int half = 0; half < 2; half++) {
                int r  = tileM + wm * 32 + mf * 16 + qd + half * 8;
                int cc = tileN + wn * 64 + nf * 8 + c2;
                int t = cc >> 10, rem = cc & 1023;
                int hh = rem >> 6, d = rem & 63;
                int b = r >> 10, s = r & 1023;
                float sc = (t == 1) ? 0.125f : 1.f;
                uint32_t pk = pack_bf162(acc[mf][nf][half*2] * sc,
                                         acc[mf][nf][half*2+1] * sc);
                bf16* dst = ((t == 0) ? g_k : (t == 1) ? g_q : g_v)
                            + (((size_t)(b * NHc + hh)) * Sc + s) * DHc + d;
                *(uint32_t*)dst = pk;
            }
}

// attn-out: x_res = x + gate_msa*acc ; sumsq_attn (vectorized f32x2)
__global__ void __launch_bounds__(256, 2) k_attnout(const float* __restrict__ x_in) {
    extern __shared__ char dsm[];
    float* sm8 = (float*)(dsm + 98304);
    float acc[2][8][4];
    gemm_core(g_y, g_woT, Hc, blockIdx.y * 128, blockIdx.x * 128, dsm, acc);
    GEMM_EPI_COORDS
    float ss = 0.f;
    #pragma unroll
    for (int mf = 0; mf < 2; mf++)
        #pragma unroll
        for (int nf = 0; nf < 8; nf++)
            #pragma unroll
            for (int half = 0; half < 2; half++) {
                int r  = tileM + wm * 32 + mf * 16 + qd + half * 8;
                int cc = tileN + wn * 64 + nf * 8 + c2;
                int b = r >> 10;
                size_t idx = (size_t)r * Hc + cc;
                float2 g2 = *(const float2*)&g_cm[b * 6 * Hc + 2 * Hc + cc];
                float2 xv = *(const float2*)&x_in[idx];
                float a0 = g2.x * acc[mf][nf][half*2];
                float a1 = g2.y * acc[mf][nf][half*2+1];
                *(float2*)&g_xres[idx] = make_float2(xv.x + a0, xv.y + a1);
                ss += a0 * a0 + a1 * a1;
            }
    float t = block_sum256(ss, sm8);
    if (threadIdx.x == 0) atomicAdd(&g_acc[2], t);
}

// mlp1: positive counts, sumsq_relu, tanh-gelu -> bf16 h (packed 4B stores)
__global__ void __launch_bounds__(256, 2) k_mlp1() {
    extern __shared__ char dsm[];
    float* sm8 = (float*)(dsm + 98304);
    int* scnt = (int*)(dsm + 98368);
    if (threadIdx.x < 128) scnt[threadIdx.x] = 0;
    float acc[2][8][4];
    gemm_core(g_xmod, g_w1T, Hc, blockIdx.y * 128, blockIdx.x * 128, dsm, acc);
    GEMM_EPI_COORDS
    float ss = 0.f;
    #pragma unroll
    for (int nf = 0; nf < 8; nf++) {
        int cnt0 = 0, cnt1 = 0;
        #pragma unroll
        for (int mf = 0; mf < 2; mf++)
            #pragma unroll
            for (int half = 0; half < 2; half++) {
                float t0 = acc[mf][nf][half*2], t1 = acc[mf][nf][half*2+1];
                ss += t0 * t0 + t1 * t1;
                cnt0 += (t0 > 0.f); cnt1 += (t1 > 0.f);
                float u0 = 0.7978845608028654f * (t0 + 0.044715f * t0 * t0 * t0);
                float u1 = 0.7978845608028654f * (t1 + 0.044715f * t1 * t1 * t1);
                float g0 = 0.5f * t0 * (1.f + tanhf(u0));
                float g1 = 0.5f * t1 * (1.f + tanhf(u1));
                int r  = tileM + wm * 32 + mf * 16 + qd + half * 8;
                int cc = tileN + wn * 64 + nf * 8 + c2;
                *(uint32_t*)&g_h[(size_t)r * MLPc + cc] = pack_bf162(g0, g1);
            }
        atomicAdd(&scnt[wn * 64 + nf * 8 + c2], cnt0);
        atomicAdd(&scnt[wn * 64 + nf * 8 + c2 + 1], cnt1);
    }
    __syncthreads();
    if (threadIdx.x < 128) atomicAdd(&g_pos[tileN + threadIdx.x], scnt[threadIdx.x]);
    float t = block_sum256(ss, sm8);
    if (threadIdx.x == 0) atomicAdd(&g_acc[4], t);
}

// mlp2: out = x_res + gate_mlp*acc ; sumsq_mlp (vectorized f32x2)
__global__ void __launch_bounds__(256, 2) k_mlp2(float* __restrict__ out) {
    extern __shared__ char dsm[];
    float* sm8 = (float*)(dsm + 98304);
    float acc[2][8][4];
    gemm_core(g_h, g_w2T, MLPc, blockIdx.y * 128, blockIdx.x * 128, dsm, acc);
    GEMM_EPI_COORDS
    float ss = 0.f;
    #pragma unroll
    for (int mf = 0; mf < 2; mf++)
        #pragma unroll
        for (int nf = 0; nf < 8; nf++)
            #pragma unroll
            for (int half = 0; half < 2; half++) {
                int r  = tileM + wm * 32 + mf * 16 + qd + half * 8;
                int cc = tileN + wn * 64 + nf * 8 + c2;
                int b = r >> 10;
                size_t idx = (size_t)r * Hc + cc;
                float2 g2 = *(const float2*)&g_cm[b * 6 * Hc + 5 * Hc + cc];
                float2 xr = *(const float2*)&g_xres[idx];
                float m0 = g2.x * acc[mf][nf][half*2];
                float m1 = g2.y * acc[mf][nf][half*2+1];
                *(float2*)&out[idx] = make_float2(xr.x + m0, xr.y + m1);
                ss += m0 * m0 + m1 * m1;
            }
    float t = block_sum256(ss, sm8);
    if (threadIdx.x == 0) atomicAdd(&g_acc[5], t);
}

// ---------------- flash attention: cp.async double-buffered + ldmatrix ----------------
// smem: Q @0 (16KB), K @16384 (+buf*8192), V @32768 (+buf*8192), sm8 @49152
#define ATT_SMEM 49216
__global__ void __launch_bounds__(256, 2) k_attn() {
    extern __shared__ char dsm[];
    uint32_t sb = smem_u32(dsm);
    uint32_t Qs = sb, Ks = sb + 16384, Vs = sb + 32768;
    float* sm8 = (float*)(dsm + 49152);
    const int tid = threadIdx.x, lane = tid & 31, w = tid >> 5;
    const int g = lane >> 3, lr = lane & 7;
    const int bh = blockIdx.y, qt = blockIdx.x;

    const bf16* Qg = g_q + ((size_t)bh * Sc + qt * 128) * DHc;
    const bf16* Kg = g_k + (size_t)bh * Sc * DHc;
    const bf16* Vg = g_v + (size_t)bh * Sc * DHc;

    #pragma unroll
    for (int t = 0; t < 4; t++) {
        int ch = tid + t * 256;
        int row = ch >> 3, c = ch & 7;
        cp_async16(sw_addr(Qs, row, c), Qg + (size_t)row * DHc + c * 8);
    }
    #pragma unroll
    for (int t = 0; t < 2; t++) {
        int ch = tid + t * 256;
        int row = ch >> 3, c = ch & 7;
        cp_async16(sw_addr(Ks, row, c), Kg + (size_t)row * DHc + c * 8);
        cp_async16(sw_addr(Vs, row, c), Vg + (size_t)row * DHc + c * 8);
    }
    CP_COMMIT;

    uint32_t qa[4][4];
    float O[8][4];
    #pragma unroll
    for (int nf = 0; nf < 8; nf++)
        #pragma unroll
        for (int i = 0; i < 4; i++) O[nf][i] = 0.f;
    float m0 = -1e30f, m1 = -1e30f, l0 = 0.f, l1 = 0.f;

    for (int kt = 0; kt < Sc / 64; kt++) {
        if (kt + 1 < Sc / 64) {
            int buf = (kt + 1) & 1;
            const bf16* Kn = Kg + (size_t)(kt + 1) * 64 * DHc;
            const bf16* Vn = Vg + (size_t)(kt + 1) * 64 * DHc;
            #pragma unroll
            for (int t = 0; t < 2; t++) {
                int ch = tid + t * 256;
                int row = ch >> 3, c = ch & 7;
                cp_async16(sw_addr(Ks + buf * 8192, row, c), Kn + (size_t)row * DHc + c * 8);
                cp_async16(sw_addr(Vs + buf * 8192, row, c), Vn + (size_t)row * DHc + c * 8);
            }
            CP_COMMIT;
            CP_WAIT1;
        } else {
            CP_WAIT0;
        }
        __syncthreads();
        if (kt == 0) {
            #pragma unroll
            for (int kk = 0; kk < 4; kk++)
                ldsm4(qa[kk], sw_addr(Qs, w * 16 + (g & 1) * 8 + lr, kk * 2 + (g >> 1)));
        }
        uint32_t kb = Ks + (kt & 1) * 8192;
        uint32_t vb = Vs + (kt & 1) * 8192;

        float L[8][4];
        #pragma unroll
        for (int nf = 0; nf < 8; nf++)
            #pragma unroll
            for (int i = 0; i < 4; i++) L[nf][i] = 0.f;
        #pragma unroll
        for (int kk = 0; kk < 4; kk++) {
            #pragma unroll
            for (int p = 0; p < 4; p++) {
                uint32_t b[4];
                ldsm4(b, sw_addr(kb, p * 16 + (g & 1) * 8 + lr, kk * 2 + (g >> 1)));
                mma16816(L[2*p],   qa[kk], b[0], b[2]);
                mma16816(L[2*p+1], qa[kk], b[1], b[3]);
            }
        }
        float tm0 = -1e30f, tm1 = -1e30f;
        #pragma unroll
        for (int nf = 0; nf < 8; nf++) {
            tm0 = fmaxf(tm0, fmaxf(L[nf][0], L[nf][1]));
            tm1 = fmaxf(tm1, fmaxf(L[nf][2], L[nf][3]));
        }
        tm0 = fmaxf(tm0, __shfl_xor_sync(0xffffffffu, tm0, 1));
        tm0 = fmaxf(tm0, __shfl_xor_sync(0xffffffffu, tm0, 2));
        tm1 = fmaxf(tm1, __shfl_xor_sync(0xffffffffu, tm1, 1));
        tm1 = fmaxf(tm1, __shfl_xor_sync(0xffffffffu, tm1, 2));
        float mn0 = fmaxf(m0, tm0), mn1 = fmaxf(m1, tm1);
        float cor0 = __expf(m0 - mn0), cor1 = __expf(m1 - mn1);
        float s0 = 0.f, s1 = 0.f;
        #pragma unroll
        for (int nf = 0; nf < 8; nf++) {
            L[nf][0] = __expf(L[nf][0] - mn0);
            L[nf][1] = __expf(L[nf][1] - mn0);
            L[nf][2] = __expf(L[nf][2] - mn1);
            L[nf][3] = __expf(L[nf][3] - mn1);
            s0 += L[nf][0] + L[nf][1];
            s1 += L[nf][2] + L[nf][3];
        }
        s0 += __shfl_xor_sync(0xffffffffu, s0, 1);
        s0 += __shfl_xor_sync(0xffffffffu, s0, 2);
        s1 += __shfl_xor_sync(0xffffffffu, s1, 1);
        s1 += __shfl_xor_sync(0xffffffffu, s1, 2);
        l0 = l0 * cor0 + s0; l1 = l1 * cor1 + s1;
        m0 = mn0; m1 = mn1;
        #pragma unroll
        for (int nf = 0; nf < 8; nf++) {
            O[nf][0] *= cor0; O[nf][1] *= cor0;
            O[nf][2] *= cor1; O[nf][3] *= cor1;
        }
        uint32_t pa[4][4];
        #pragma unroll
        for (int kk = 0; kk < 4; kk++) {
            pa[kk][0] = pack_bf162(L[2*kk][0],   L[2*kk][1]);
            pa[kk][1] = pack_bf162(L[2*kk][2],   L[2*kk][3]);
            pa[kk][2] = pack_bf162(L[2*kk+1][0], L[2*kk+1][1]);
            pa[kk][3] = pack_bf162(L[2*kk+1][2], L[2*kk+1][3]);
        }
        #pragma unroll
        for (int kk = 0; kk < 4; kk++) {
            #pragma unroll
            for (int p = 0; p < 4; p++) {
                uint32_t b[4];
                ldsm4t(b, sw_addr(vb, kk * 16 + (g & 1) * 8 + lr, p * 2 + (g >> 1)));
                mma16816(O[2*p],   pa[kk], b[0], b[1]);
                mma16816(O[2*p+1], pa[kk], b[2], b[3]);
            }
        }
        __syncthreads();
    }
    const int qd = lane >> 2, c2 = (lane & 3) << 1;
    float i0 = 1.f / l0, i1 = 1.f / l1;
    int b = bh >> 4, hh = bh & 15;
    int r0 = qt * 128 + w * 16 + qd;
    #pragma unroll
    for (int nf = 0; nf < 8; nf++) {
        size_t base0 = ((size_t)b * Sc + r0)     * Hc + hh * 64 + nf * 8 + c2;
        size_t base1 = ((size_t)b * Sc + r0 + 8) * Hc + hh * 64 + nf * 8 + c2;
        *(uint32_t*)&g_y[base0] = pack_bf162(O[nf][0] * i0, O[nf][1] * i0);
        *(uint32_t*)&g_y[base1] = pack_bf162(O[nf][2] * i1, O[nf][3] * i1);
    }
    float contrib = ((lane & 3) == 0) ? (i0 + i1) : 0.f;
    float t = block_sum256(contrib, sm8);
    if (tid == 0) atomicAdd(&g_acc[1], t);
}

// ---------------- finalize scalars ----------------
__global__ void k_fin(float* __restrict__ out, int out_size) {
    __shared__ float sm8[8];
    int tid = threadIdx.x;
    float dsum = 0.f; int zc = 0, pc = 0;
    for (int j = tid; j < MLPc; j += 256) {
        int c = g_pos[j];
        float fp = c * (1.f / 8192.f);
        dsum += fabsf(fp - 0.5f);
        zc += (c == 0);
        pc += (c == 8192);
    }
    float d = block_sum256(dsum, sm8);
    float z = block_sum256((float)zc, sm8);
    float p = block_sum256((float)pc, sm8);
    if (tid == 0 && out_size != MROWS * Hc) {
        float* o = out + (out_size - 7);
        o[0] = d * (1.f / 4096.f);
        o[1] = z * (1.f / 4096.f);
        o[2] = p * (1.f / 4096.f);
        o[3] = g_acc[1] * (1.f / 131072.f);
        o[4] = sqrtf(g_acc[2] / g_acc[0]);
        o[5] = sqrtf(g_acc[5] / g_acc[3]);
        o[6] = sqrtf(g_acc[4] / (8192.f * 4096.f));
    }
}

// ---------------- launch ----------------
extern "C" void kernel_launch(void* const* d_in, const int* in_sizes, int n_in,
                              void* d_out, int out_size) {
    const float* x      = (const float*)d_in[0];
    const float* c      = (const float*)d_in[1];
    const float* w_cond = (const float*)d_in[2];
    const float* w_qkv  = (const float*)d_in[3];
    const float* w_attn = (const float*)d_in[4];
    const float* w_mlp1 = (const float*)d_in[5];
    const float* w_mlp2 = (const float*)d_in[6];
    float* out = (float*)d_out;

    cudaFuncSetAttribute(k_qkv,     cudaFuncAttributeMaxDynamicSharedMemorySize, SMEM_G);
    cudaFuncSetAttribute(k_attnout, cudaFuncAttributeMaxDynamicSharedMemorySize, SMEM_G);
    cudaFuncSetAttribute(k_mlp1,    cudaFuncAttributeMaxDynamicSharedMemorySize, SMEM_G);
    cudaFuncSetAttribute(k_mlp2,    cudaFuncAttributeMaxDynamicSharedMemorySize, SMEM_G);
    cudaFuncSetAttribute(k_attn,    cudaFuncAttributeMaxDynamicSharedMemorySize, ATT_SMEM);

    k_zero<<<192, 256>>>();
    k_trans<<<dim3(96, 32),  256>>>(w_qkv,  0, Hc,   3*Hc);
    k_trans<<<dim3(32, 32),  256>>>(w_attn, 1, Hc,   Hc);
    k_trans<<<dim3(128, 32), 256>>>(w_mlp1, 2, Hc,   MLPc);
    k_trans<<<dim3(32, 128), 256>>>(w_mlp2, 3, MLPc, Hc);
    k_cond<<<dim3(24, 8), 256>>>(c, w_cond);
    k_ln_w<<<MROWS / 8, 256>>>(x, 0, 0, 1, 0);
    k_qkv<<<dim3(24, 64), 256, SMEM_G>>>();
    k_attn<<<dim3(8, Bc * NHc), 256, ATT_SMEM>>>();
    k_attnout<<<dim3(8, 64), 256, SMEM_G>>>(x);
    k_ln_w<<<MROWS / 8, 256>>>(x, 1, 3, 4, 3);
    k_mlp1<<<dim3(32, 64), 256, SMEM_G>>>();
    k_mlp2<<<dim3(8, 64), 256, SMEM_G>>>(out);
    k_fin<<<1, 256>>>(out, out_size);
}